// round 2
// baseline (speedup 1.0000x reference)
#include <cuda_runtime.h>
#include <cuda_bf16.h>
#include <math.h>

// ---------------------------------------------------------------------------
// Problem constants
// ---------------------------------------------------------------------------
#define S_LEN     2048
#define HIDDEN    4096
#define NUM_HEADS 32
#define NUM_KVH   8
#define HEAD_DIM  128
#define Q_SIZE    (NUM_HEADS * HEAD_DIM)       // 4096
#define KV_SIZE   (NUM_KVH * HEAD_DIM)         // 1024
#define QKV_OUT   (Q_SIZE + 2 * KV_SIZE)       // 6144

// Scratch (device globals; no allocations allowed)
__device__ float g_qkv[S_LEN * QKV_OUT];       // 50.3 MB
__device__ float g_attn[S_LEN * Q_SIZE];       // 33.5 MB

// ---------------------------------------------------------------------------
// Generic NT SGEMM: C[M,N] = A[M,K] * B[N,K]^T   (both K-major, row-major)
// 128x128 block tile, BK=8, 8x8 thread tile, 256 threads
// ---------------------------------------------------------------------------
__global__ __launch_bounds__(256) void sgemm_nt(
    const float* __restrict__ A, const float* __restrict__ B,
    float* __restrict__ C, int M, int N, int K)
{
    __shared__ float As[8][128];
    __shared__ float Bs[8][128];

    const int tid = threadIdx.x;
    const int ty  = tid >> 4;   // 0..15 -> row group
    const int tx  = tid & 15;   // 0..15 -> col group

    const float* Ablk = A + (size_t)blockIdx.y * 128 * K;
    const float* Bblk = B + (size_t)blockIdx.x * 128 * K;

    const int lRow = tid >> 1;          // 0..127
    const int lCol = (tid & 1) * 4;     // 0 or 4

    float acc[8][8];
#pragma unroll
    for (int i = 0; i < 8; i++)
#pragma unroll
        for (int j = 0; j < 8; j++) acc[i][j] = 0.0f;

    for (int k0 = 0; k0 < K; k0 += 8) {
        float4 a4 = *(const float4*)(Ablk + (size_t)lRow * K + k0 + lCol);
        float4 b4 = *(const float4*)(Bblk + (size_t)lRow * K + k0 + lCol);
        As[lCol + 0][lRow] = a4.x; As[lCol + 1][lRow] = a4.y;
        As[lCol + 2][lRow] = a4.z; As[lCol + 3][lRow] = a4.w;
        Bs[lCol + 0][lRow] = b4.x; Bs[lCol + 1][lRow] = b4.y;
        Bs[lCol + 2][lRow] = b4.z; Bs[lCol + 3][lRow] = b4.w;
        __syncthreads();

#pragma unroll
        for (int k = 0; k < 8; k++) {
            float4 a0 = *(const float4*)&As[k][ty * 8];
            float4 a1 = *(const float4*)&As[k][ty * 8 + 4];
            float4 b0 = *(const float4*)&Bs[k][tx * 8];
            float4 b1 = *(const float4*)&Bs[k][tx * 8 + 4];
            float ra[8] = {a0.x, a0.y, a0.z, a0.w, a1.x, a1.y, a1.z, a1.w};
            float rb[8] = {b0.x, b0.y, b0.z, b0.w, b1.x, b1.y, b1.z, b1.w};
#pragma unroll
            for (int i = 0; i < 8; i++)
#pragma unroll
                for (int j = 0; j < 8; j++)
                    acc[i][j] = fmaf(ra[i], rb[j], acc[i][j]);
        }
        __syncthreads();
    }

#pragma unroll
    for (int i = 0; i < 8; i++) {
        int row = blockIdx.y * 128 + ty * 8 + i;
        float* cp = C + (size_t)row * N + blockIdx.x * 128 + tx * 8;
        float4 c0 = {acc[i][0], acc[i][1], acc[i][2], acc[i][3]};
        float4 c1 = {acc[i][4], acc[i][5], acc[i][6], acc[i][7]};
        *(float4*)cp = c0;
        *(float4*)(cp + 4) = c1;
    }
}

// ---------------------------------------------------------------------------
// RoPE (in place on Q and K sections of g_qkv). Angles in double for accuracy.
// ---------------------------------------------------------------------------
__global__ void rope_kernel(float* __restrict__ qkv)
{
    int idx = blockIdx.x * blockDim.x + threadIdx.x;
    const int total = S_LEN * (NUM_HEADS + NUM_KVH) * 64;   // pairs
    if (idx >= total) return;
    int i = idx & 63;
    int h = (idx >> 6) % (NUM_HEADS + NUM_KVH);
    int s = idx / (64 * (NUM_HEADS + NUM_KVH));
    int base = s * QKV_OUT + (h < NUM_HEADS ? h * HEAD_DIM
                                            : Q_SIZE + (h - NUM_HEADS) * HEAD_DIM);
    float x1 = qkv[base + i];
    float x2 = qkv[base + 64 + i];
    double freq = pow(10000.0, -(double)(2 * i) / 128.0);
    double ang  = (double)s * freq;
    double sa, ca;
    sincos(ang, &sa, &ca);
    float c = (float)ca, sn = (float)sa;
    qkv[base + i]      = x1 * c  - x2 * sn;
    qkv[base + 64 + i] = x1 * sn + x2 * c;
}

// ---------------------------------------------------------------------------
// Flash attention (fp32, causal, GQA). Block = 64 q-rows x 1 head, 128 thr.
// Thread layout: ty(0..7) owns 8 q-rows, tx(0..15) owns 4 score-cols / 8 d-cols.
// ---------------------------------------------------------------------------
#define FA_SMEM ((3 * 64 * 129 + 64 * 65) * 4)

__global__ __launch_bounds__(128) void flash_kernel(
    const float* __restrict__ qkv, float* __restrict__ attn_out)
{
    extern __shared__ float sm[];
    float* Qs = sm;                  // [64][129]
    float* Ks = Qs + 64 * 129;       // [64][129]
    float* Vs = Ks + 64 * 129;       // [64][129]
    float* Ps = Vs + 64 * 129;       // [64][65]

    const int tid  = threadIdx.x;
    const int ty   = tid >> 4;   // 0..7
    const int tx   = tid & 15;   // 0..15
    const int q0   = blockIdx.x * 64;
    const int head = blockIdx.y;
    const int kvh  = head >> 2;
    const float scale = 0.088388347648318447f;   // 1/sqrt(128)

    // Load Q tile (after RoPE)
    for (int e = tid; e < 64 * 32; e += 128) {
        int r = e >> 5, c4 = (e & 31) * 4;
        float4 v = *(const float4*)(qkv + (size_t)(q0 + r) * QKV_OUT + head * HEAD_DIM + c4);
        float* dst = &Qs[r * 129 + c4];
        dst[0] = v.x; dst[1] = v.y; dst[2] = v.z; dst[3] = v.w;
    }

    float o[8][8];
#pragma unroll
    for (int i = 0; i < 8; i++)
#pragma unroll
        for (int j = 0; j < 8; j++) o[i][j] = 0.0f;
    float m_[8], l_[8];
#pragma unroll
    for (int i = 0; i < 8; i++) { m_[i] = -1e30f; l_[i] = 0.0f; }

    const int ntiles = q0 / 64 + 1;
    for (int t = 0; t < ntiles; t++) {
        const int j0 = t * 64;
        __syncthreads();
        for (int e = tid; e < 64 * 32; e += 128) {
            int r = e >> 5, c4 = (e & 31) * 4;
            const float* kp = qkv + (size_t)(j0 + r) * QKV_OUT + Q_SIZE + kvh * HEAD_DIM + c4;
            float4 k4 = *(const float4*)kp;
            float4 v4 = *(const float4*)(kp + KV_SIZE);
            float* kd = &Ks[r * 129 + c4];
            float* vd = &Vs[r * 129 + c4];
            kd[0] = k4.x; kd[1] = k4.y; kd[2] = k4.z; kd[3] = k4.w;
            vd[0] = v4.x; vd[1] = v4.y; vd[2] = v4.z; vd[3] = v4.w;
        }
        __syncthreads();

        // S = Q K^T
        float s_[8][4];
#pragma unroll
        for (int i = 0; i < 8; i++)
#pragma unroll
            for (int j = 0; j < 4; j++) s_[i][j] = 0.0f;

        for (int d = 0; d < 128; d++) {
            float kr[4];
#pragma unroll
            for (int jj = 0; jj < 4; jj++) kr[jj] = Ks[(tx * 4 + jj) * 129 + d];
#pragma unroll
            for (int ii = 0; ii < 8; ii++) {
                float qv = Qs[(ty * 8 + ii) * 129 + d];
#pragma unroll
                for (int jj = 0; jj < 4; jj++)
                    s_[ii][jj] = fmaf(qv, kr[jj], s_[ii][jj]);
            }
        }

        // masked online softmax
#pragma unroll
        for (int ii = 0; ii < 8; ii++) {
            const int gi = q0 + ty * 8 + ii;
            float mt = -1e30f;
#pragma unroll
            for (int jj = 0; jj < 4; jj++) {
                int gj = j0 + tx * 4 + jj;
                float v = s_[ii][jj] * scale;
                if (gj > gi) v = -1e30f;
                s_[ii][jj] = v;
                mt = fmaxf(mt, v);
            }
#pragma unroll
            for (int msk = 8; msk >= 1; msk >>= 1)
                mt = fmaxf(mt, __shfl_xor_sync(0xffffffffu, mt, msk));
            float mnew  = fmaxf(m_[ii], mt);
            float alpha = __expf(m_[ii] - mnew);
            float ls = 0.0f;
#pragma unroll
            for (int jj = 0; jj < 4; jj++) {
                float p = __expf(s_[ii][jj] - mnew);
                s_[ii][jj] = p;
                ls += p;
            }
#pragma unroll
            for (int msk = 8; msk >= 1; msk >>= 1)
                ls += __shfl_xor_sync(0xffffffffu, ls, msk);
            l_[ii] = l_[ii] * alpha + ls;
            m_[ii] = mnew;
#pragma unroll
            for (int dd = 0; dd < 8; dd++) o[ii][dd] *= alpha;
#pragma unroll
            for (int jj = 0; jj < 4; jj++)
                Ps[(ty * 8 + ii) * 65 + tx * 4 + jj] = s_[ii][jj];
        }
        __syncwarp();

        // O += P V
        for (int j = 0; j < 64; j++) {
            float vv[8];
#pragma unroll
            for (int dd = 0; dd < 8; dd++) vv[dd] = Vs[j * 129 + dd * 16 + tx];
#pragma unroll
            for (int ii = 0; ii < 8; ii++) {
                float p = Ps[(ty * 8 + ii) * 65 + j];
#pragma unroll
                for (int dd = 0; dd < 8; dd++)
                    o[ii][dd] = fmaf(p, vv[dd], o[ii][dd]);
            }
        }
        __syncwarp();
    }

#pragma unroll
    for (int ii = 0; ii < 8; ii++) {
        float inv = 1.0f / l_[ii];
        int gi = q0 + ty * 8 + ii;
#pragma unroll
        for (int dd = 0; dd < 8; dd++)
            attn_out[(size_t)gi * Q_SIZE + head * HEAD_DIM + dd * 16 + tx] = o[ii][dd] * inv;
    }
}

// ---------------------------------------------------------------------------
// Launch
// ---------------------------------------------------------------------------
extern "C" void kernel_launch(void* const* d_in, const int* in_sizes, int n_in,
                              void* d_out, int out_size)
{
    const float* hidden = (const float*)d_in[0];
    const float* w_qkv  = (const float*)d_in[1];
    const float* w_o    = (const float*)d_in[2];
    float* out = (float*)d_out;

    float *qkv, *attn;
    cudaGetSymbolAddress((void**)&qkv,  g_qkv);
    cudaGetSymbolAddress((void**)&attn, g_attn);

    // 1. QKV projection: [2048,6144] = hidden[2048,4096] @ w_qkv[6144,4096]^T
    sgemm_nt<<<dim3(QKV_OUT / 128, S_LEN / 128), 256>>>(hidden, w_qkv, qkv,
                                                        S_LEN, QKV_OUT, HIDDEN);
    // 2. RoPE in place on Q and K sections
    {
        int total = S_LEN * (NUM_HEADS + NUM_KVH) * 64;
        rope_kernel<<<(total + 255) / 256, 256>>>(qkv);
    }
    // 3. Flash attention
    cudaFuncSetAttribute(flash_kernel, cudaFuncAttributeMaxDynamicSharedMemorySize, FA_SMEM);
    flash_kernel<<<dim3(S_LEN / 64, NUM_HEADS), 128, FA_SMEM>>>(qkv, attn);
    // 4. Output projection: [2048,4096] = attn[2048,4096] @ w_o[4096,4096]^T
    sgemm_nt<<<dim3(HIDDEN / 128, S_LEN / 128), 256>>>(attn, w_o, out,
                                                       S_LEN, HIDDEN, HIDDEN);
}

// round 4
// speedup vs baseline: 1.7721x; 1.7721x over previous
#include <cuda_runtime.h>
#include <cuda_bf16.h>
#include <math.h>
#include <stdint.h>

// ---------------------------------------------------------------------------
// Problem constants
// ---------------------------------------------------------------------------
#define S_LEN     2048
#define HIDDEN    4096
#define NUM_HEADS 32
#define NUM_KVH   8
#define HEAD_DIM  128
#define Q_SIZE    (NUM_HEADS * HEAD_DIM)       // 4096
#define KV_SIZE   (NUM_KVH * HEAD_DIM)         // 1024
#define QKV_OUT   (Q_SIZE + 2 * KV_SIZE)       // 6144

// Scratch (device globals; no allocations allowed)
__device__ float         g_qkv[S_LEN * QKV_OUT];
__device__ __nv_bfloat16 g_hid_hi[S_LEN * HIDDEN];
__device__ __nv_bfloat16 g_hid_lo[S_LEN * HIDDEN];
__device__ __nv_bfloat16 g_wqkv_hi[QKV_OUT * HIDDEN];
__device__ __nv_bfloat16 g_wqkv_lo[QKV_OUT * HIDDEN];
__device__ __nv_bfloat16 g_wo_hi[HIDDEN * HIDDEN];
__device__ __nv_bfloat16 g_wo_lo[HIDDEN * HIDDEN];
__device__ __nv_bfloat16 g_attn_hi[S_LEN * Q_SIZE];
__device__ __nv_bfloat16 g_attn_lo[S_LEN * Q_SIZE];

// ---------------------------------------------------------------------------
// PTX helpers: cp.async + ldmatrix + mma.sync (all valid on base sm_103)
// ---------------------------------------------------------------------------
__device__ __forceinline__ uint32_t smem_u32(const void* p) {
    uint32_t a;
    asm("{ .reg .u64 t; cvta.to.shared.u64 t, %1; cvt.u32.u64 %0, t; }"
        : "=r"(a) : "l"(p));
    return a;
}
__device__ __forceinline__ void cp16(uint32_t dst, const void* src) {
    asm volatile("cp.async.cg.shared.global [%0], [%1], 16;"
                 :: "r"(dst), "l"(src));
}
#define CP_COMMIT()  asm volatile("cp.async.commit_group;" ::: "memory")
#define CP_WAIT(n)   asm volatile("cp.async.wait_group %0;" :: "n"(n) : "memory")

__device__ __forceinline__ void ldsm4(uint32_t& r0, uint32_t& r1,
                                      uint32_t& r2, uint32_t& r3, uint32_t addr) {
    asm volatile("ldmatrix.sync.aligned.m8n8.x4.shared.b16 {%0,%1,%2,%3}, [%4];"
                 : "=r"(r0), "=r"(r1), "=r"(r2), "=r"(r3) : "r"(addr));
}
__device__ __forceinline__ void mma_bf16(float* d, const uint32_t* a, const uint32_t* b) {
    asm volatile(
        "mma.sync.aligned.m16n8k16.row.col.f32.bf16.bf16.f32 "
        "{%0,%1,%2,%3},{%4,%5,%6,%7},{%8,%9},{%0,%1,%2,%3};"
        : "+f"(d[0]), "+f"(d[1]), "+f"(d[2]), "+f"(d[3])
        : "r"(a[0]), "r"(a[1]), "r"(a[2]), "r"(a[3]), "r"(b[0]), "r"(b[1]));
}

// ---------------------------------------------------------------------------
// Split fp32 -> (hi, lo) bf16
// ---------------------------------------------------------------------------
__global__ void split_kernel(const float* __restrict__ x,
                             __nv_bfloat16* __restrict__ hi,
                             __nv_bfloat16* __restrict__ lo, int n)
{
    int i = (blockIdx.x * blockDim.x + threadIdx.x) * 4;
    if (i >= n) return;
    float4 v = *(const float4*)(x + i);
    __nv_bfloat16 h0 = __float2bfloat16_rn(v.x);
    __nv_bfloat16 h1 = __float2bfloat16_rn(v.y);
    __nv_bfloat16 h2 = __float2bfloat16_rn(v.z);
    __nv_bfloat16 h3 = __float2bfloat16_rn(v.w);
    __nv_bfloat16 l0 = __float2bfloat16_rn(v.x - __bfloat162float(h0));
    __nv_bfloat16 l1 = __float2bfloat16_rn(v.y - __bfloat162float(h1));
    __nv_bfloat16 l2 = __float2bfloat16_rn(v.z - __bfloat162float(h2));
    __nv_bfloat16 l3 = __float2bfloat16_rn(v.w - __bfloat162float(h3));
    __nv_bfloat162* hp = (__nv_bfloat162*)(hi + i);
    __nv_bfloat162* lp = (__nv_bfloat162*)(lo + i);
    hp[0] = __nv_bfloat162(h0, h1); hp[1] = __nv_bfloat162(h2, h3);
    lp[0] = __nv_bfloat162(l0, l1); lp[1] = __nv_bfloat162(l2, l3);
}

// ---------------------------------------------------------------------------
// Split-bf16 x3 warp-MMA GEMM: C[M,N] = (Ahi+Alo)[M,K] * (Bhi+Blo)[N,K]^T
// 128x128 CTA tile, 8 warps (4M x 2N), warp tile 32x64, K-chunk 32,
// cp.async double-buffered smem, ldmatrix + mma.sync m16n8k16 bf16.
// ---------------------------------------------------------------------------
#define ROWB      80                      // padded row pitch (bytes): conflict-free
#define TILE_SM   (128 * ROWB)            // 10240 B per tile
#define STAGE_SM  (4 * TILE_SM)           // Ahi, Alo, Bhi, Blo
#define GEMM_SMEM (2 * STAGE_SM)          // 81920 B

__global__ __launch_bounds__(256) void gemm_bf16x3(
    const __nv_bfloat16* __restrict__ Ahi, const __nv_bfloat16* __restrict__ Alo,
    const __nv_bfloat16* __restrict__ Bhi, const __nv_bfloat16* __restrict__ Blo,
    float* __restrict__ C, int M, int N, int K)
{
    extern __shared__ __align__(128) char smem[];
    const uint32_t sb0 = smem_u32(smem);
    const int tid  = threadIdx.x;
    const int lane = tid & 31;
    const int wid  = tid >> 5;
    const int wm   = wid & 3;         // 0..3  -> m offset wm*32
    const int wn   = wid >> 2;        // 0..1  -> n offset wn*64
    const int rowBlk = blockIdx.y * 128;
    const int colBlk = blockIdx.x * 128;

    const size_t gstride = (size_t)K * 2;  // bytes/row
    const char* gsrc[4] = {
        (const char*)(Ahi + (size_t)rowBlk * K),
        (const char*)(Alo + (size_t)rowBlk * K),
        (const char*)(Bhi + (size_t)colBlk * K),
        (const char*)(Blo + (size_t)colBlk * K)
    };

    float acc[2][8][4];
#pragma unroll
    for (int i = 0; i < 2; i++)
#pragma unroll
        for (int j = 0; j < 8; j++)
#pragma unroll
            for (int k = 0; k < 4; k++) acc[i][j][k] = 0.0f;

    const int nch = K / 32;

    // ---- load issue: one 32-wide K chunk (64 B/row), 4 tiles, into stage st
    auto issue = [&](int c, int st) {
        const uint32_t stg = sb0 + st * STAGE_SM;
#pragma unroll
        for (int t = 0; t < 4; t++) {
#pragma unroll
            for (int u = 0; u < 2; u++) {
                int e   = tid + u * 256;          // 0..511
                int row = e >> 2;
                int ch  = (e & 3) * 16;
                cp16(stg + t * TILE_SM + row * ROWB + ch,
                     gsrc[t] + (size_t)row * gstride + (size_t)c * 64 + ch);
            }
        }
        CP_COMMIT();
    };

    issue(0, 0);

    for (int c = 0; c < nch; c++) {
        const int st = c & 1;
        if (c + 1 < nch) { issue(c + 1, st ^ 1); CP_WAIT(1); }
        else             { CP_WAIT(0); }
        __syncthreads();

        const uint32_t sA_hi = sb0 + st * STAGE_SM;
        const uint32_t sA_lo = sA_hi + TILE_SM;
        const uint32_t sB_hi = sA_hi + 2 * TILE_SM;
        const uint32_t sB_lo = sA_hi + 3 * TILE_SM;

#pragma unroll
        for (int ks = 0; ks < 2; ks++) {
            const uint32_t akb = ks * 32 + (lane >> 4) * 16;          // A k-byte off
            const uint32_t bkb = ks * 32 + ((lane >> 3) & 1) * 16;    // B k-byte off

            uint32_t ah[2][4], al[2][4];
#pragma unroll
            for (int am = 0; am < 2; am++) {
                uint32_t ro = (uint32_t)(wm * 32 + am * 16 + (lane & 15)) * ROWB + akb;
                ldsm4(ah[am][0], ah[am][1], ah[am][2], ah[am][3], sA_hi + ro);
                ldsm4(al[am][0], al[am][1], al[am][2], al[am][3], sA_lo + ro);
            }
            uint32_t bh[8][2], bl[8][2];
#pragma unroll
            for (int bp = 0; bp < 4; bp++) {
                uint32_t ro = (uint32_t)(wn * 64 + bp * 16 + (lane >> 4) * 8 + (lane & 7)) * ROWB + bkb;
                ldsm4(bh[2*bp][0], bh[2*bp][1], bh[2*bp+1][0], bh[2*bp+1][1], sB_hi + ro);
                ldsm4(bl[2*bp][0], bl[2*bp][1], bl[2*bp+1][0], bl[2*bp+1][1], sB_lo + ro);
            }
#pragma unroll
            for (int am = 0; am < 2; am++)
#pragma unroll
                for (int bn = 0; bn < 8; bn++) {
                    mma_bf16(acc[am][bn], ah[am], bh[bn]);
                    mma_bf16(acc[am][bn], ah[am], bl[bn]);
                    mma_bf16(acc[am][bn], al[am], bh[bn]);
                }
        }
        __syncthreads();
    }

    // ---- epilogue: direct fp32 stores (float2 per atom-row)
#pragma unroll
    for (int am = 0; am < 2; am++) {
        int r0 = rowBlk + wm * 32 + am * 16 + (lane >> 2);
#pragma unroll
        for (int bn = 0; bn < 8; bn++) {
            int col = colBlk + wn * 64 + bn * 8 + (lane & 3) * 2;
            float2 v0 = {acc[am][bn][0], acc[am][bn][1]};
            float2 v1 = {acc[am][bn][2], acc[am][bn][3]};
            *(float2*)(C + (size_t)r0 * N + col)       = v0;
            *(float2*)(C + (size_t)(r0 + 8) * N + col) = v1;
        }
    }
}

// ---------------------------------------------------------------------------
// RoPE (in place on Q and K sections of g_qkv). Angles in double for accuracy.
// ---------------------------------------------------------------------------
__global__ void rope_kernel(float* __restrict__ qkv)
{
    int idx = blockIdx.x * blockDim.x + threadIdx.x;
    const int total = S_LEN * (NUM_HEADS + NUM_KVH) * 64;   // pairs
    if (idx >= total) return;
    int i = idx & 63;
    int h = (idx >> 6) % (NUM_HEADS + NUM_KVH);
    int s = idx / (64 * (NUM_HEADS + NUM_KVH));
    int base = s * QKV_OUT + (h < NUM_HEADS ? h * HEAD_DIM
                                            : Q_SIZE + (h - NUM_HEADS) * HEAD_DIM);
    float x1 = qkv[base + i];
    float x2 = qkv[base + 64 + i];
    double freq = pow(10000.0, -(double)(2 * i) / 128.0);
    double ang  = (double)s * freq;
    double sa, ca;
    sincos(ang, &sa, &ca);
    float c = (float)ca, sn = (float)sa;
    qkv[base + i]      = x1 * c  - x2 * sn;
    qkv[base + 64 + i] = x1 * sn + x2 * c;
}

// ---------------------------------------------------------------------------
// Flash attention (fp32, causal, GQA). Block = 64 q-rows x 1 head, 128 thr.
// Writes split bf16 (hi, lo) so the O-proj GEMM consumes it directly.
// ---------------------------------------------------------------------------
#define FA_SMEM ((3 * 64 * 129 + 64 * 65) * 4)

__global__ __launch_bounds__(128) void flash_kernel(
    const float* __restrict__ qkv,
    __nv_bfloat16* __restrict__ out_hi, __nv_bfloat16* __restrict__ out_lo)
{
    extern __shared__ float sm[];
    float* Qs = sm;                  // [64][129]
    float* Ks = Qs + 64 * 129;       // [64][129]
    float* Vs = Ks + 64 * 129;       // [64][129]
    float* Ps = Vs + 64 * 129;       // [64][65]

    const int tid  = threadIdx.x;
    const int ty   = tid >> 4;   // 0..7
    const int tx   = tid & 15;   // 0..15
    const int q0   = blockIdx.x * 64;
    const int head = blockIdx.y;
    const int kvh  = head >> 2;
    const float scale = 0.088388347648318447f;   // 1/sqrt(128)

    for (int e = tid; e < 64 * 32; e += 128) {
        int r = e >> 5, c4 = (e & 31) * 4;
        float4 v = *(const float4*)(qkv + (size_t)(q0 + r) * QKV_OUT + head * HEAD_DIM + c4);
        float* dst = &Qs[r * 129 + c4];
        dst[0] = v.x; dst[1] = v.y; dst[2] = v.z; dst[3] = v.w;
    }

    float o[8][8];
#pragma unroll
    for (int i = 0; i < 8; i++)
#pragma unroll
        for (int j = 0; j < 8; j++) o[i][j] = 0.0f;
    float m_[8], l_[8];
#pragma unroll
    for (int i = 0; i < 8; i++) { m_[i] = -1e30f; l_[i] = 0.0f; }

    const int ntiles = q0 / 64 + 1;
    for (int t = 0; t < ntiles; t++) {
        const int j0 = t * 64;
        __syncthreads();
        for (int e = tid; e < 64 * 32; e += 128) {
            int r = e >> 5, c4 = (e & 31) * 4;
            const float* kp = qkv + (size_t)(j0 + r) * QKV_OUT + Q_SIZE + kvh * HEAD_DIM + c4;
            float4 k4 = *(const float4*)kp;
            float4 v4 = *(const float4*)(kp + KV_SIZE);
            float* kd = &Ks[r * 129 + c4];
            float* vd = &Vs[r * 129 + c4];
            kd[0] = k4.x; kd[1] = k4.y; kd[2] = k4.z; kd[3] = k4.w;
            vd[0] = v4.x; vd[1] = v4.y; vd[2] = v4.z; vd[3] = v4.w;
        }
        __syncthreads();

        float s_[8][4];
#pragma unroll
        for (int i = 0; i < 8; i++)
#pragma unroll
            for (int j = 0; j < 4; j++) s_[i][j] = 0.0f;

        for (int d = 0; d < 128; d++) {
            float kr[4];
#pragma unroll
            for (int jj = 0; jj < 4; jj++) kr[jj] = Ks[(tx * 4 + jj) * 129 + d];
#pragma unroll
            for (int ii = 0; ii < 8; ii++) {
                float qv = Qs[(ty * 8 + ii) * 129 + d];
#pragma unroll
                for (int jj = 0; jj < 4; jj++)
                    s_[ii][jj] = fmaf(qv, kr[jj], s_[ii][jj]);
            }
        }

#pragma unroll
        for (int ii = 0; ii < 8; ii++) {
            const int gi = q0 + ty * 8 + ii;
            float mt = -1e30f;
#pragma unroll
            for (int jj = 0; jj < 4; jj++) {
                int gj = j0 + tx * 4 + jj;
                float v = s_[ii][jj] * scale;
                if (gj > gi) v = -1e30f;
                s_[ii][jj] = v;
                mt = fmaxf(mt, v);
            }
#pragma unroll
            for (int msk = 8; msk >= 1; msk >>= 1)
                mt = fmaxf(mt, __shfl_xor_sync(0xffffffffu, mt, msk));
            float mnew  = fmaxf(m_[ii], mt);
            float alpha = __expf(m_[ii] - mnew);
            float ls = 0.0f;
#pragma unroll
            for (int jj = 0; jj < 4; jj++) {
                float p = __expf(s_[ii][jj] - mnew);
                s_[ii][jj] = p;
                ls += p;
            }
#pragma unroll
            for (int msk = 8; msk >= 1; msk >>= 1)
                ls += __shfl_xor_sync(0xffffffffu, ls, msk);
            l_[ii] = l_[ii] * alpha + ls;
            m_[ii] = mnew;
#pragma unroll
            for (int dd = 0; dd < 8; dd++) o[ii][dd] *= alpha;
#pragma unroll
            for (int jj = 0; jj < 4; jj++)
                Ps[(ty * 8 + ii) * 65 + tx * 4 + jj] = s_[ii][jj];
        }
        __syncwarp();

        for (int j = 0; j < 64; j++) {
            float vv[8];
#pragma unroll
            for (int dd = 0; dd < 8; dd++) vv[dd] = Vs[j * 129 + dd * 16 + tx];
#pragma unroll
            for (int ii = 0; ii < 8; ii++) {
                float p = Ps[(ty * 8 + ii) * 65 + j];
#pragma unroll
                for (int dd = 0; dd < 8; dd++)
                    o[ii][dd] = fmaf(p, vv[dd], o[ii][dd]);
            }
        }
        __syncwarp();
    }

#pragma unroll
    for (int ii = 0; ii < 8; ii++) {
        float inv = 1.0f / l_[ii];
        int gi = q0 + ty * 8 + ii;
#pragma unroll
        for (int dd = 0; dd < 8; dd++) {
            float val = o[ii][dd] * inv;
            __nv_bfloat16 h = __float2bfloat16_rn(val);
            __nv_bfloat16 l = __float2bfloat16_rn(val - __bfloat162float(h));
            size_t idx = (size_t)gi * Q_SIZE + head * HEAD_DIM + dd * 16 + tx;
            out_hi[idx] = h;
            out_lo[idx] = l;
        }
    }
}

// ---------------------------------------------------------------------------
// Launch
// ---------------------------------------------------------------------------
extern "C" void kernel_launch(void* const* d_in, const int* in_sizes, int n_in,
                              void* d_out, int out_size)
{
    const float* hidden = (const float*)d_in[0];
    const float* w_qkv  = (const float*)d_in[1];
    const float* w_o    = (const float*)d_in[2];
    float* out = (float*)d_out;

    float* qkv;
    __nv_bfloat16 *hh, *hl, *qh, *ql, *oh, *ol, *ah, *al;
    cudaGetSymbolAddress((void**)&qkv, g_qkv);
    cudaGetSymbolAddress((void**)&hh, g_hid_hi);
    cudaGetSymbolAddress((void**)&hl, g_hid_lo);
    cudaGetSymbolAddress((void**)&qh, g_wqkv_hi);
    cudaGetSymbolAddress((void**)&ql, g_wqkv_lo);
    cudaGetSymbolAddress((void**)&oh, g_wo_hi);
    cudaGetSymbolAddress((void**)&ol, g_wo_lo);
    cudaGetSymbolAddress((void**)&ah, g_attn_hi);
    cudaGetSymbolAddress((void**)&al, g_attn_lo);

    cudaFuncSetAttribute(gemm_bf16x3, cudaFuncAttributeMaxDynamicSharedMemorySize, GEMM_SMEM);
    cudaFuncSetAttribute(flash_kernel, cudaFuncAttributeMaxDynamicSharedMemorySize, FA_SMEM);

    // 0. split inputs into hi/lo bf16
    {
        int n1 = S_LEN * HIDDEN;
        split_kernel<<<n1 / 4 / 256, 256>>>(hidden, hh, hl, n1);
        int n2 = QKV_OUT * HIDDEN;
        split_kernel<<<n2 / 4 / 256, 256>>>(w_qkv, qh, ql, n2);
        int n3 = HIDDEN * HIDDEN;
        split_kernel<<<n3 / 4 / 256, 256>>>(w_o, oh, ol, n3);
    }
    // 1. QKV projection (tensor cores): [2048,6144] = hidden @ w_qkv^T
    gemm_bf16x3<<<dim3(QKV_OUT / 128, S_LEN / 128), 256, GEMM_SMEM>>>(
        hh, hl, qh, ql, qkv, S_LEN, QKV_OUT, HIDDEN);
    // 2. RoPE in place on Q and K sections
    {
        int total = S_LEN * (NUM_HEADS + NUM_KVH) * 64;
        rope_kernel<<<(total + 255) / 256, 256>>>(qkv);
    }
    // 3. Flash attention (fp32) -> split bf16 output
    flash_kernel<<<dim3(S_LEN / 64, NUM_HEADS), 128, FA_SMEM>>>(qkv, ah, al);
    // 4. Output projection (tensor cores): [2048,4096] = attn @ w_o^T
    gemm_bf16x3<<<dim3(HIDDEN / 128, S_LEN / 128), 256, GEMM_SMEM>>>(
        ah, al, oh, ol, out, S_LEN, HIDDEN, HIDDEN);
}

// round 5
// speedup vs baseline: 3.4892x; 1.9690x over previous
#include <cuda_runtime.h>
#include <cuda_bf16.h>
#include <math.h>
#include <stdint.h>

// ---------------------------------------------------------------------------
// Problem constants
// ---------------------------------------------------------------------------
#define S_LEN     2048
#define HIDDEN    4096
#define NUM_HEADS 32
#define NUM_KVH   8
#define HEAD_DIM  128
#define Q_SIZE    (NUM_HEADS * HEAD_DIM)       // 4096
#define KV_SIZE   (NUM_KVH * HEAD_DIM)         // 1024
#define QKV_OUT   (Q_SIZE + 2 * KV_SIZE)       // 6144

// Scratch (device globals; no allocations allowed)
__device__ float         g_qkv[S_LEN * QKV_OUT];
__device__ __nv_bfloat16 g_hid_hi[S_LEN * HIDDEN];
__device__ __nv_bfloat16 g_hid_lo[S_LEN * HIDDEN];
__device__ __nv_bfloat16 g_wqkv_hi[QKV_OUT * HIDDEN];
__device__ __nv_bfloat16 g_wqkv_lo[QKV_OUT * HIDDEN];
__device__ __nv_bfloat16 g_wo_hi[HIDDEN * HIDDEN];
__device__ __nv_bfloat16 g_wo_lo[HIDDEN * HIDDEN];
__device__ __nv_bfloat16 g_attn_hi[S_LEN * Q_SIZE];
__device__ __nv_bfloat16 g_attn_lo[S_LEN * Q_SIZE];
// RoPE'd, head-major, split bf16 Q/K/V for the flash kernel
__device__ __nv_bfloat16 g_q_hi[NUM_HEADS * S_LEN * HEAD_DIM];
__device__ __nv_bfloat16 g_q_lo[NUM_HEADS * S_LEN * HEAD_DIM];
__device__ __nv_bfloat16 g_k_hi[NUM_KVH * S_LEN * HEAD_DIM];
__device__ __nv_bfloat16 g_k_lo[NUM_KVH * S_LEN * HEAD_DIM];
__device__ __nv_bfloat16 g_v_hi[NUM_KVH * S_LEN * HEAD_DIM];
__device__ __nv_bfloat16 g_v_lo[NUM_KVH * S_LEN * HEAD_DIM];
__device__ float         g_cos[S_LEN * 64];
__device__ float         g_sin[S_LEN * 64];

// ---------------------------------------------------------------------------
// PTX helpers: cp.async + ldmatrix + mma.sync (base sm_103 compatible)
// ---------------------------------------------------------------------------
__device__ __forceinline__ uint32_t smem_u32(const void* p) {
    uint32_t a;
    asm("{ .reg .u64 t; cvta.to.shared.u64 t, %1; cvt.u32.u64 %0, t; }"
        : "=r"(a) : "l"(p));
    return a;
}
__device__ __forceinline__ void cp16(uint32_t dst, const void* src) {
    asm volatile("cp.async.cg.shared.global [%0], [%1], 16;"
                 :: "r"(dst), "l"(src));
}
#define CP_COMMIT()  asm volatile("cp.async.commit_group;" ::: "memory")
#define CP_WAIT(n)   asm volatile("cp.async.wait_group %0;" :: "n"(n) : "memory")

__device__ __forceinline__ void ldsm4(uint32_t& r0, uint32_t& r1,
                                      uint32_t& r2, uint32_t& r3, uint32_t addr) {
    asm volatile("ldmatrix.sync.aligned.m8n8.x4.shared.b16 {%0,%1,%2,%3}, [%4];"
                 : "=r"(r0), "=r"(r1), "=r"(r2), "=r"(r3) : "r"(addr));
}
__device__ __forceinline__ void ldsm4t(uint32_t& r0, uint32_t& r1,
                                       uint32_t& r2, uint32_t& r3, uint32_t addr) {
    asm volatile("ldmatrix.sync.aligned.m8n8.x4.trans.shared.b16 {%0,%1,%2,%3}, [%4];"
                 : "=r"(r0), "=r"(r1), "=r"(r2), "=r"(r3) : "r"(addr));
}
__device__ __forceinline__ void mma_bf16(float* d, const uint32_t* a, const uint32_t* b) {
    asm volatile(
        "mma.sync.aligned.m16n8k16.row.col.f32.bf16.bf16.f32 "
        "{%0,%1,%2,%3},{%4,%5,%6,%7},{%8,%9},{%0,%1,%2,%3};"
        : "+f"(d[0]), "+f"(d[1]), "+f"(d[2]), "+f"(d[3])
        : "r"(a[0]), "r"(a[1]), "r"(a[2]), "r"(a[3]), "r"(b[0]), "r"(b[1]));
}
__device__ __forceinline__ uint32_t packbf(__nv_bfloat16 a, __nv_bfloat16 b) {
    return ((uint32_t)__bfloat16_as_ushort(b) << 16) | __bfloat16_as_ushort(a);
}
// split two floats -> packed hi pair + packed lo pair
__device__ __forceinline__ void split2(float a, float b, uint32_t& hi, uint32_t& lo) {
    __nv_bfloat16 ha = __float2bfloat16_rn(a), hb = __float2bfloat16_rn(b);
    __nv_bfloat16 la = __float2bfloat16_rn(a - __bfloat162float(ha));
    __nv_bfloat16 lb = __float2bfloat16_rn(b - __bfloat162float(hb));
    hi = packbf(ha, hb); lo = packbf(la, lb);
}

// ---------------------------------------------------------------------------
// Split fp32 -> (hi, lo) bf16
// ---------------------------------------------------------------------------
__global__ void split_kernel(const float* __restrict__ x,
                             __nv_bfloat16* __restrict__ hi,
                             __nv_bfloat16* __restrict__ lo, int n)
{
    int i = (blockIdx.x * blockDim.x + threadIdx.x) * 4;
    if (i >= n) return;
    float4 v = *(const float4*)(x + i);
    uint32_t h0, l0, h1, l1;
    split2(v.x, v.y, h0, l0);
    split2(v.z, v.w, h1, l1);
    uint32_t* hp = (uint32_t*)(hi + i);
    uint32_t* lp = (uint32_t*)(lo + i);
    hp[0] = h0; hp[1] = h1;
    lp[0] = l0; lp[1] = l1;
}

// ---------------------------------------------------------------------------
// Split-bf16 x3 warp-MMA GEMM: C[M,N] = (Ahi+Alo)[M,K] * (Bhi+Blo)[N,K]^T
// ---------------------------------------------------------------------------
#define ROWB      80
#define TILE_SM   (128 * ROWB)
#define STAGE_SM  (4 * TILE_SM)
#define GEMM_SMEM (2 * STAGE_SM)

__global__ __launch_bounds__(256) void gemm_bf16x3(
    const __nv_bfloat16* __restrict__ Ahi, const __nv_bfloat16* __restrict__ Alo,
    const __nv_bfloat16* __restrict__ Bhi, const __nv_bfloat16* __restrict__ Blo,
    float* __restrict__ C, int M, int N, int K)
{
    extern __shared__ __align__(128) char smem[];
    const uint32_t sb0 = smem_u32(smem);
    const int tid  = threadIdx.x;
    const int lane = tid & 31;
    const int wid  = tid >> 5;
    const int wm   = wid & 3;
    const int wn   = wid >> 2;
    const int rowBlk = blockIdx.y * 128;
    const int colBlk = blockIdx.x * 128;

    const size_t gstride = (size_t)K * 2;
    const char* gsrc[4] = {
        (const char*)(Ahi + (size_t)rowBlk * K),
        (const char*)(Alo + (size_t)rowBlk * K),
        (const char*)(Bhi + (size_t)colBlk * K),
        (const char*)(Blo + (size_t)colBlk * K)
    };

    float acc[2][8][4];
#pragma unroll
    for (int i = 0; i < 2; i++)
#pragma unroll
        for (int j = 0; j < 8; j++)
#pragma unroll
            for (int k = 0; k < 4; k++) acc[i][j][k] = 0.0f;

    const int nch = K / 32;

    auto issue = [&](int c, int st) {
        const uint32_t stg = sb0 + st * STAGE_SM;
#pragma unroll
        for (int t = 0; t < 4; t++) {
#pragma unroll
            for (int u = 0; u < 2; u++) {
                int e   = tid + u * 256;
                int row = e >> 2;
                int ch  = (e & 3) * 16;
                cp16(stg + t * TILE_SM + row * ROWB + ch,
                     gsrc[t] + (size_t)row * gstride + (size_t)c * 64 + ch);
            }
        }
        CP_COMMIT();
    };

    issue(0, 0);

    for (int c = 0; c < nch; c++) {
        const int st = c & 1;
        if (c + 1 < nch) { issue(c + 1, st ^ 1); CP_WAIT(1); }
        else             { CP_WAIT(0); }
        __syncthreads();

        const uint32_t sA_hi = sb0 + st * STAGE_SM;
        const uint32_t sA_lo = sA_hi + TILE_SM;
        const uint32_t sB_hi = sA_hi + 2 * TILE_SM;
        const uint32_t sB_lo = sA_hi + 3 * TILE_SM;

#pragma unroll
        for (int ks = 0; ks < 2; ks++) {
            const uint32_t akb = ks * 32 + (lane >> 4) * 16;
            const uint32_t bkb = ks * 32 + ((lane >> 3) & 1) * 16;

            uint32_t ah[2][4], al[2][4];
#pragma unroll
            for (int am = 0; am < 2; am++) {
                uint32_t ro = (uint32_t)(wm * 32 + am * 16 + (lane & 15)) * ROWB + akb;
                ldsm4(ah[am][0], ah[am][1], ah[am][2], ah[am][3], sA_hi + ro);
                ldsm4(al[am][0], al[am][1], al[am][2], al[am][3], sA_lo + ro);
            }
            uint32_t bh[8][2], bl[8][2];
#pragma unroll
            for (int bp = 0; bp < 4; bp++) {
                uint32_t ro = (uint32_t)(wn * 64 + bp * 16 + (lane >> 4) * 8 + (lane & 7)) * ROWB + bkb;
                ldsm4(bh[2*bp][0], bh[2*bp][1], bh[2*bp+1][0], bh[2*bp+1][1], sB_hi + ro);
                ldsm4(bl[2*bp][0], bl[2*bp][1], bl[2*bp+1][0], bl[2*bp+1][1], sB_lo + ro);
            }
#pragma unroll
            for (int am = 0; am < 2; am++)
#pragma unroll
                for (int bn = 0; bn < 8; bn++) {
                    mma_bf16(acc[am][bn], ah[am], bh[bn]);
                    mma_bf16(acc[am][bn], ah[am], bl[bn]);
                    mma_bf16(acc[am][bn], al[am], bh[bn]);
                }
        }
        __syncthreads();
    }

#pragma unroll
    for (int am = 0; am < 2; am++) {
        int r0 = rowBlk + wm * 32 + am * 16 + (lane >> 2);
#pragma unroll
        for (int bn = 0; bn < 8; bn++) {
            int col = colBlk + wn * 64 + bn * 8 + (lane & 3) * 2;
            float2 v0 = {acc[am][bn][0], acc[am][bn][1]};
            float2 v1 = {acc[am][bn][2], acc[am][bn][3]};
            *(float2*)(C + (size_t)r0 * N + col)       = v0;
            *(float2*)(C + (size_t)(r0 + 8) * N + col) = v1;
        }
    }
}

// ---------------------------------------------------------------------------
// RoPE cos/sin table (double precision -> fp32)
// ---------------------------------------------------------------------------
__global__ void rope_table(float* __restrict__ cost, float* __restrict__ sint)
{
    int idx = blockIdx.x * blockDim.x + threadIdx.x;
    if (idx >= S_LEN * 64) return;
    int i = idx & 63;
    int s = idx >> 6;
    double freq = pow(10000.0, -2.0 * i / 128.0);
    double sa, ca;
    sincos((double)s * freq, &sa, &ca);
    cost[idx] = (float)ca;
    sint[idx] = (float)sa;
}

// ---------------------------------------------------------------------------
// RoPE + split into head-major bf16 hi/lo arrays (Q,K rotated; V split only)
// ---------------------------------------------------------------------------
__global__ void rope_split(const float* __restrict__ qkv,
                           const float* __restrict__ cost, const float* __restrict__ sint,
                           __nv_bfloat16* __restrict__ qh, __nv_bfloat16* __restrict__ ql,
                           __nv_bfloat16* __restrict__ kh, __nv_bfloat16* __restrict__ kl,
                           __nv_bfloat16* __restrict__ vh, __nv_bfloat16* __restrict__ vl)
{
    int idx = blockIdx.x * blockDim.x + threadIdx.x;
    const int total = S_LEN * 48 * 64;
    if (idx >= total) return;
    int i = idx & 63;
    int h = (idx >> 6) % 48;
    int s = idx / (64 * 48);

    auto wsplit = [](float v, __nv_bfloat16* hi, __nv_bfloat16* lo, size_t d) {
        __nv_bfloat16 hv = __float2bfloat16_rn(v);
        hi[d] = hv;
        lo[d] = __float2bfloat16_rn(v - __bfloat162float(hv));
    };

    if (h < 40) {   // Q heads 0..31, K heads 32..39 : rotate then split
        const float* src; __nv_bfloat16 *dh, *dl; size_t d;
        if (h < NUM_HEADS) {
            src = qkv + (size_t)s * QKV_OUT + h * HEAD_DIM;
            dh = qh; dl = ql;
            d = ((size_t)h * S_LEN + s) * HEAD_DIM + i;
        } else {
            int hk = h - NUM_HEADS;
            src = qkv + (size_t)s * QKV_OUT + Q_SIZE + hk * HEAD_DIM;
            dh = kh; dl = kl;
            d = ((size_t)hk * S_LEN + s) * HEAD_DIM + i;
        }
        float x1 = src[i], x2 = src[i + 64];
        float c = cost[s * 64 + i], sn = sint[s * 64 + i];
        wsplit(x1 * c - x2 * sn, dh, dl, d);
        wsplit(x1 * sn + x2 * c, dh, dl, d + 64);
    } else {        // V heads: split only
        int hv = h - 40;
        const float* src = qkv + (size_t)s * QKV_OUT + Q_SIZE + KV_SIZE + hv * HEAD_DIM;
        size_t d = ((size_t)hv * S_LEN + s) * HEAD_DIM + i;
        wsplit(src[i], vh, vl, d);
        wsplit(src[i + 64], vh, vl, d + 64);
    }
}

// ---------------------------------------------------------------------------
// Tensor-core flash attention (causal, GQA), split-bf16 x3 for S and PV.
// Block = 64 q-rows x 1 head, 4 warps. Warp owns 16 q-rows.
// ---------------------------------------------------------------------------
#define FP  272                      // smem row pitch (bytes), conflict-free
#define FT  (64 * FP)                // one 64x128 bf16 tile = 17408 B
#define FLASH_SMEM (6 * FT)          // Qh Ql Kh Kl Vh Vl = 104448 B

__global__ __launch_bounds__(128, 2) void flash_mma(
    const __nv_bfloat16* __restrict__ qh_g, const __nv_bfloat16* __restrict__ ql_g,
    const __nv_bfloat16* __restrict__ kh_g, const __nv_bfloat16* __restrict__ kl_g,
    const __nv_bfloat16* __restrict__ vh_g, const __nv_bfloat16* __restrict__ vl_g,
    __nv_bfloat16* __restrict__ out_hi, __nv_bfloat16* __restrict__ out_lo)
{
    extern __shared__ __align__(128) char sm[];
    const uint32_t Qh = smem_u32(sm);
    const uint32_t Ql = Qh + FT;
    const uint32_t Kh = Qh + 2 * FT;
    const uint32_t Kl = Qh + 3 * FT;
    const uint32_t Vh = Qh + 4 * FT;
    const uint32_t Vl = Qh + 5 * FT;

    const int tid  = threadIdx.x;
    const int lane = tid & 31;
    const int w    = tid >> 5;
    const int qt   = gridDim.x - 1 - blockIdx.x;   // heavy tiles first
    const int q0   = qt * 64;
    const int head = blockIdx.y;
    const int kvh  = head >> 2;
    const float scale = 0.088388347648318447f;

    // ---- load Q tile (split bf16, head-major source, 256B rows)
    {
        const char* sh = (const char*)(qh_g + ((size_t)head * S_LEN + q0) * HEAD_DIM);
        const char* sl = (const char*)(ql_g + ((size_t)head * S_LEN + q0) * HEAD_DIM);
#pragma unroll
        for (int i = 0; i < 8; i++) {
            int e = tid + i * 128;
            int r = e >> 4, ch = (e & 15) * 16;
            cp16(Qh + r * FP + ch, sh + (size_t)r * 256 + ch);
            cp16(Ql + r * FP + ch, sl + (size_t)r * 256 + ch);
        }
        CP_COMMIT(); CP_WAIT(0);
    }
    __syncthreads();

    float o[16][4];
#pragma unroll
    for (int d = 0; d < 16; d++)
#pragma unroll
        for (int c = 0; c < 4; c++) o[d][c] = 0.0f;
    float m_lo = -1e30f, m_hi = -1e30f, l_lo = 0.0f, l_hi = 0.0f;

    const int gi_lo = q0 + w * 16 + (lane >> 2);
    const int gi_hi = gi_lo + 8;

    const char* kh_src = (const char*)(kh_g + (size_t)kvh * S_LEN * HEAD_DIM);
    const char* kl_src = (const char*)(kl_g + (size_t)kvh * S_LEN * HEAD_DIM);
    const char* vh_src = (const char*)(vh_g + (size_t)kvh * S_LEN * HEAD_DIM);
    const char* vl_src = (const char*)(vl_g + (size_t)kvh * S_LEN * HEAD_DIM);

    const int ntiles = qt + 1;
    for (int t = 0; t < ntiles; t++) {
        const int j0 = t * 64;
        // ---- load K/V tiles
#pragma unroll
        for (int i = 0; i < 8; i++) {
            int e = tid + i * 128;
            int r = e >> 4, ch = (e & 15) * 16;
            size_t so = (size_t)(j0 + r) * 256 + ch;
            uint32_t dof = r * FP + ch;
            cp16(Kh + dof, kh_src + so);
            cp16(Kl + dof, kl_src + so);
            cp16(Vh + dof, vh_src + so);
            cp16(Vl + dof, vl_src + so);
        }
        CP_COMMIT(); CP_WAIT(0);
        __syncthreads();

        // ---- S = Q K^T (3-term split), warp rows w*16..+16, cols 0..64
        float sacc[8][4];
#pragma unroll
        for (int bn = 0; bn < 8; bn++)
#pragma unroll
            for (int c = 0; c < 4; c++) sacc[bn][c] = 0.0f;

#pragma unroll
        for (int ks = 0; ks < 8; ks++) {
            uint32_t aoff = (uint32_t)(w * 16 + (lane & 15)) * FP + ks * 32 + (lane >> 4) * 16;
            uint32_t a_h[4], a_l[4];
            ldsm4(a_h[0], a_h[1], a_h[2], a_h[3], Qh + aoff);
            ldsm4(a_l[0], a_l[1], a_l[2], a_l[3], Ql + aoff);
#pragma unroll
            for (int bp = 0; bp < 4; bp++) {
                uint32_t koff = (uint32_t)(bp * 16 + (lane >> 4) * 8 + (lane & 7)) * FP
                              + ks * 32 + ((lane >> 3) & 1) * 16;
                uint32_t bh[4], bl[4];
                ldsm4(bh[0], bh[1], bh[2], bh[3], Kh + koff);
                ldsm4(bl[0], bl[1], bl[2], bl[3], Kl + koff);
                mma_bf16(sacc[2*bp],   a_h, &bh[0]);
                mma_bf16(sacc[2*bp],   a_h, &bl[0]);
                mma_bf16(sacc[2*bp],   a_l, &bh[0]);
                mma_bf16(sacc[2*bp+1], a_h, &bh[2]);
                mma_bf16(sacc[2*bp+1], a_h, &bl[2]);
                mma_bf16(sacc[2*bp+1], a_l, &bh[2]);
            }
        }

        // ---- masked online softmax (fp32 in fragments)
        const bool need_mask = (j0 == q0);
        float mx0 = m_lo, mx1 = m_hi;
#pragma unroll
        for (int bn = 0; bn < 8; bn++) {
            int gj = j0 + bn * 8 + (lane & 3) * 2;
            float s0 = sacc[bn][0] * scale, s1 = sacc[bn][1] * scale;
            float s2 = sacc[bn][2] * scale, s3 = sacc[bn][3] * scale;
            if (need_mask) {
                if (gj     > gi_lo) s0 = -1e30f;
                if (gj + 1 > gi_lo) s1 = -1e30f;
                if (gj     > gi_hi) s2 = -1e30f;
                if (gj + 1 > gi_hi) s3 = -1e30f;
            }
            sacc[bn][0] = s0; sacc[bn][1] = s1; sacc[bn][2] = s2; sacc[bn][3] = s3;
            mx0 = fmaxf(mx0, fmaxf(s0, s1));
            mx1 = fmaxf(mx1, fmaxf(s2, s3));
        }
        mx0 = fmaxf(mx0, __shfl_xor_sync(0xffffffffu, mx0, 1));
        mx0 = fmaxf(mx0, __shfl_xor_sync(0xffffffffu, mx0, 2));
        mx1 = fmaxf(mx1, __shfl_xor_sync(0xffffffffu, mx1, 1));
        mx1 = fmaxf(mx1, __shfl_xor_sync(0xffffffffu, mx1, 2));

        float alpha0 = __expf(m_lo - mx0);
        float alpha1 = __expf(m_hi - mx1);
        float sum0 = 0.0f, sum1 = 0.0f;
#pragma unroll
        for (int bn = 0; bn < 8; bn++) {
            float p0 = __expf(sacc[bn][0] - mx0);
            float p1 = __expf(sacc[bn][1] - mx0);
            float p2 = __expf(sacc[bn][2] - mx1);
            float p3 = __expf(sacc[bn][3] - mx1);
            sacc[bn][0] = p0; sacc[bn][1] = p1; sacc[bn][2] = p2; sacc[bn][3] = p3;
            sum0 += p0 + p1; sum1 += p2 + p3;
        }
        sum0 += __shfl_xor_sync(0xffffffffu, sum0, 1);
        sum0 += __shfl_xor_sync(0xffffffffu, sum0, 2);
        sum1 += __shfl_xor_sync(0xffffffffu, sum1, 1);
        sum1 += __shfl_xor_sync(0xffffffffu, sum1, 2);
        l_lo = l_lo * alpha0 + sum0;
        l_hi = l_hi * alpha1 + sum1;
        m_lo = mx0; m_hi = mx1;
#pragma unroll
        for (int d = 0; d < 16; d++) {
            o[d][0] *= alpha0; o[d][1] *= alpha0;
            o[d][2] *= alpha1; o[d][3] *= alpha1;
        }

        // ---- O += P V (3-term split); P frags come straight from sacc
#pragma unroll
        for (int ks2 = 0; ks2 < 4; ks2++) {
            uint32_t ah[4], al[4];
            split2(sacc[2*ks2][0],   sacc[2*ks2][1],   ah[0], al[0]);
            split2(sacc[2*ks2][2],   sacc[2*ks2][3],   ah[1], al[1]);
            split2(sacc[2*ks2+1][0], sacc[2*ks2+1][1], ah[2], al[2]);
            split2(sacc[2*ks2+1][2], sacc[2*ks2+1][3], ah[3], al[3]);
#pragma unroll
            for (int vp = 0; vp < 8; vp++) {
                uint32_t voff = (uint32_t)(ks2 * 16 + ((lane >> 3) & 1) * 8 + (lane & 7)) * FP
                              + (vp * 16 + (lane >> 4) * 8) * 2;
                uint32_t bh[4], bl[4];
                ldsm4t(bh[0], bh[1], bh[2], bh[3], Vh + voff);
                ldsm4t(bl[0], bl[1], bl[2], bl[3], Vl + voff);
                mma_bf16(o[2*vp],   ah, &bh[0]);
                mma_bf16(o[2*vp],   ah, &bl[0]);
                mma_bf16(o[2*vp],   al, &bh[0]);
                mma_bf16(o[2*vp+1], ah, &bh[2]);
                mma_bf16(o[2*vp+1], ah, &bl[2]);
                mma_bf16(o[2*vp+1], al, &bh[2]);
            }
        }
        __syncthreads();
    }

    // ---- epilogue: normalize, split, write
    float inv0 = 1.0f / l_lo, inv1 = 1.0f / l_hi;
    size_t base0 = (size_t)gi_lo * Q_SIZE + head * HEAD_DIM + (lane & 3) * 2;
    size_t base1 = base0 + (size_t)8 * Q_SIZE;
#pragma unroll
    for (int d = 0; d < 16; d++) {
        uint32_t h0, l0, h1, l1;
        split2(o[d][0] * inv0, o[d][1] * inv0, h0, l0);
        split2(o[d][2] * inv1, o[d][3] * inv1, h1, l1);
        *(uint32_t*)(out_hi + base0 + d * 8) = h0;
        *(uint32_t*)(out_lo + base0 + d * 8) = l0;
        *(uint32_t*)(out_hi + base1 + d * 8) = h1;
        *(uint32_t*)(out_lo + base1 + d * 8) = l1;
    }
}

// ---------------------------------------------------------------------------
// Launch
// ---------------------------------------------------------------------------
extern "C" void kernel_launch(void* const* d_in, const int* in_sizes, int n_in,
                              void* d_out, int out_size)
{
    const float* hidden = (const float*)d_in[0];
    const float* w_qkv  = (const float*)d_in[1];
    const float* w_o    = (const float*)d_in[2];
    float* out = (float*)d_out;

    float *qkv, *cost, *sint;
    __nv_bfloat16 *hh, *hl, *wqh, *wql, *woh, *wol, *ah, *al;
    __nv_bfloat16 *qh, *ql, *kh, *kl, *vh, *vl;
    cudaGetSymbolAddress((void**)&qkv, g_qkv);
    cudaGetSymbolAddress((void**)&cost, g_cos);
    cudaGetSymbolAddress((void**)&sint, g_sin);
    cudaGetSymbolAddress((void**)&hh, g_hid_hi);
    cudaGetSymbolAddress((void**)&hl, g_hid_lo);
    cudaGetSymbolAddress((void**)&wqh, g_wqkv_hi);
    cudaGetSymbolAddress((void**)&wql, g_wqkv_lo);
    cudaGetSymbolAddress((void**)&woh, g_wo_hi);
    cudaGetSymbolAddress((void**)&wol, g_wo_lo);
    cudaGetSymbolAddress((void**)&ah, g_attn_hi);
    cudaGetSymbolAddress((void**)&al, g_attn_lo);
    cudaGetSymbolAddress((void**)&qh, g_q_hi);
    cudaGetSymbolAddress((void**)&ql, g_q_lo);
    cudaGetSymbolAddress((void**)&kh, g_k_hi);
    cudaGetSymbolAddress((void**)&kl, g_k_lo);
    cudaGetSymbolAddress((void**)&vh, g_v_hi);
    cudaGetSymbolAddress((void**)&vl, g_v_lo);

    cudaFuncSetAttribute(gemm_bf16x3, cudaFuncAttributeMaxDynamicSharedMemorySize, GEMM_SMEM);
    cudaFuncSetAttribute(flash_mma, cudaFuncAttributeMaxDynamicSharedMemorySize, FLASH_SMEM);

    // 0. RoPE table + input splits
    rope_table<<<(S_LEN * 64 + 255) / 256, 256>>>(cost, sint);
    {
        int n1 = S_LEN * HIDDEN;
        split_kernel<<<n1 / 4 / 256, 256>>>(hidden, hh, hl, n1);
        int n2 = QKV_OUT * HIDDEN;
        split_kernel<<<n2 / 4 / 256, 256>>>(w_qkv, wqh, wql, n2);
        int n3 = HIDDEN * HIDDEN;
        split_kernel<<<n3 / 4 / 256, 256>>>(w_o, woh, wol, n3);
    }
    // 1. QKV projection (tensor cores)
    gemm_bf16x3<<<dim3(QKV_OUT / 128, S_LEN / 128), 256, GEMM_SMEM>>>(
        hh, hl, wqh, wql, qkv, S_LEN, QKV_OUT, HIDDEN);
    // 2. RoPE + head-major split bf16
    {
        int total = S_LEN * 48 * 64;
        rope_split<<<(total + 255) / 256, 256>>>(qkv, cost, sint,
                                                 qh, ql, kh, kl, vh, vl);
    }
    // 3. Tensor-core flash attention -> split bf16 output
    flash_mma<<<dim3(S_LEN / 64, NUM_HEADS), 128, FLASH_SMEM>>>(
        qh, ql, kh, kl, vh, vl, ah, al);
    // 4. Output projection (tensor cores)
    gemm_bf16x3<<<dim3(HIDDEN / 128, S_LEN / 128), 256, GEMM_SMEM>>>(
        ah, al, woh, wol, out, S_LEN, HIDDEN, HIDDEN);
}

// round 7
// speedup vs baseline: 6.8228x; 1.9554x over previous
#include <cuda_runtime.h>
#include <cuda_bf16.h>
#include <cuda_fp16.h>
#include <math.h>
#include <stdint.h>

// ---------------------------------------------------------------------------
// Problem constants
// ---------------------------------------------------------------------------
#define S_LEN     2048
#define HIDDEN    4096
#define NUM_HEADS 32
#define NUM_KVH   8
#define HEAD_DIM  128
#define Q_SIZE    (NUM_HEADS * HEAD_DIM)       // 4096
#define KV_SIZE   (NUM_KVH * HEAD_DIM)         // 1024
#define QKV_OUT   (Q_SIZE + 2 * KV_SIZE)       // 6144

// Scratch (device globals; no allocations allowed)
__device__ float         g_qkv[S_LEN * QKV_OUT];
__device__ __half        g_hid_h[S_LEN * HIDDEN];
__device__ __half        g_wqkv_h[QKV_OUT * HIDDEN];
__device__ __half        g_wo_h[HIDDEN * HIDDEN];
__device__ __half        g_attn_h[S_LEN * Q_SIZE];
// RoPE'd, head-major, split bf16 Q/K/V for the flash kernel
__device__ __nv_bfloat16 g_q_hi[NUM_HEADS * S_LEN * HEAD_DIM];
__device__ __nv_bfloat16 g_q_lo[NUM_HEADS * S_LEN * HEAD_DIM];
__device__ __nv_bfloat16 g_k_hi[NUM_KVH * S_LEN * HEAD_DIM];
__device__ __nv_bfloat16 g_k_lo[NUM_KVH * S_LEN * HEAD_DIM];
__device__ __nv_bfloat16 g_v_hi[NUM_KVH * S_LEN * HEAD_DIM];
__device__ __nv_bfloat16 g_v_lo[NUM_KVH * S_LEN * HEAD_DIM];
__device__ float         g_cos[S_LEN * 64];
__device__ float         g_sin[S_LEN * 64];

// ---------------------------------------------------------------------------
// PTX helpers (base sm_103 compatible)
// ---------------------------------------------------------------------------
__device__ __forceinline__ uint32_t smem_u32(const void* p) {
    uint32_t a;
    asm("{ .reg .u64 t; cvta.to.shared.u64 t, %1; cvt.u32.u64 %0, t; }"
        : "=r"(a) : "l"(p));
    return a;
}
__device__ __forceinline__ void cp16(uint32_t dst, const void* src) {
    asm volatile("cp.async.cg.shared.global [%0], [%1], 16;"
                 :: "r"(dst), "l"(src));
}
#define CP_COMMIT()  asm volatile("cp.async.commit_group;" ::: "memory")
#define CP_WAIT(n)   asm volatile("cp.async.wait_group %0;" :: "n"(n) : "memory")

__device__ __forceinline__ void ldsm4(uint32_t& r0, uint32_t& r1,
                                      uint32_t& r2, uint32_t& r3, uint32_t addr) {
    asm volatile("ldmatrix.sync.aligned.m8n8.x4.shared.b16 {%0,%1,%2,%3}, [%4];"
                 : "=r"(r0), "=r"(r1), "=r"(r2), "=r"(r3) : "r"(addr));
}
__device__ __forceinline__ void ldsm4t(uint32_t& r0, uint32_t& r1,
                                       uint32_t& r2, uint32_t& r3, uint32_t addr) {
    asm volatile("ldmatrix.sync.aligned.m8n8.x4.trans.shared.b16 {%0,%1,%2,%3}, [%4];"
                 : "=r"(r0), "=r"(r1), "=r"(r2), "=r"(r3) : "r"(addr));
}
__device__ __forceinline__ void mma_bf16(float* d, const uint32_t* a, const uint32_t* b) {
    asm volatile(
        "mma.sync.aligned.m16n8k16.row.col.f32.bf16.bf16.f32 "
        "{%0,%1,%2,%3},{%4,%5,%6,%7},{%8,%9},{%0,%1,%2,%3};"
        : "+f"(d[0]), "+f"(d[1]), "+f"(d[2]), "+f"(d[3])
        : "r"(a[0]), "r"(a[1]), "r"(a[2]), "r"(a[3]), "r"(b[0]), "r"(b[1]));
}
__device__ __forceinline__ void mma_fp16(float* d, const uint32_t* a, const uint32_t* b) {
    asm volatile(
        "mma.sync.aligned.m16n8k16.row.col.f32.f16.f16.f32 "
        "{%0,%1,%2,%3},{%4,%5,%6,%7},{%8,%9},{%0,%1,%2,%3};"
        : "+f"(d[0]), "+f"(d[1]), "+f"(d[2]), "+f"(d[3])
        : "r"(a[0]), "r"(a[1]), "r"(a[2]), "r"(a[3]), "r"(b[0]), "r"(b[1]));
}
__device__ __forceinline__ uint32_t packbf(__nv_bfloat16 a, __nv_bfloat16 b) {
    return ((uint32_t)__bfloat16_as_ushort(b) << 16) | __bfloat16_as_ushort(a);
}
__device__ __forceinline__ void split2(float a, float b, uint32_t& hi, uint32_t& lo) {
    __nv_bfloat16 ha = __float2bfloat16_rn(a), hb = __float2bfloat16_rn(b);
    __nv_bfloat16 la = __float2bfloat16_rn(a - __bfloat162float(ha));
    __nv_bfloat16 lb = __float2bfloat16_rn(b - __bfloat162float(hb));
    hi = packbf(ha, hb); lo = packbf(la, lb);
}

// ---------------------------------------------------------------------------
// fp32 -> fp16 convert
// ---------------------------------------------------------------------------
__global__ void cvt_fp16(const float* __restrict__ x, __half* __restrict__ y, int n)
{
    int i = (blockIdx.x * blockDim.x + threadIdx.x) * 4;
    if (i >= n) return;
    float4 v = *(const float4*)(x + i);
    __half2* yp = (__half2*)(y + i);
    yp[0] = __floats2half2_rn(v.x, v.y);
    yp[1] = __floats2half2_rn(v.z, v.w);
}

// ---------------------------------------------------------------------------
// fp16 warp-MMA GEMM: C[M,N] = A[M,K] * B[N,K]^T   (single pass)
// 128x128 CTA tile, 8 warps (4M x 2N), warp 32x64, K-chunk 32, 4-stage pipe.
// ---------------------------------------------------------------------------
#define ROWB       80
#define TILE_SM    (128 * ROWB)             // 10240 B
#define STAGE16    (2 * TILE_SM)            // A + B = 20480 B
#define NSTAGE     4
#define GEMM_SMEM  (NSTAGE * STAGE16)       // 81920 B

__global__ __launch_bounds__(256, 2) void gemm_fp16(
    const __half* __restrict__ A, const __half* __restrict__ B,
    float* __restrict__ C, int M, int N, int K)
{
    extern __shared__ __align__(128) char smem[];
    const uint32_t sb0 = smem_u32(smem);
    const int tid  = threadIdx.x;
    const int lane = tid & 31;
    const int wid  = tid >> 5;
    const int wm   = wid & 3;
    const int wn   = wid >> 2;
    const int rowBlk = blockIdx.y * 128;
    const int colBlk = blockIdx.x * 128;

    const size_t gstride = (size_t)K * 2;
    const char* gA = (const char*)(A + (size_t)rowBlk * K);
    const char* gB = (const char*)(B + (size_t)colBlk * K);

    float acc[2][8][4];
#pragma unroll
    for (int i = 0; i < 2; i++)
#pragma unroll
        for (int j = 0; j < 8; j++)
#pragma unroll
            for (int k = 0; k < 4; k++) acc[i][j][k] = 0.0f;

    const int nch = K / 32;

    auto issue = [&](int c) {
        const uint32_t stg = sb0 + (c & (NSTAGE - 1)) * STAGE16;
#pragma unroll
        for (int u = 0; u < 2; u++) {
            int e   = tid + u * 256;          // 0..511
            int row = e >> 2;
            int ch  = (e & 3) * 16;
            cp16(stg + row * ROWB + ch,
                 gA + (size_t)row * gstride + (size_t)c * 64 + ch);
            cp16(stg + TILE_SM + row * ROWB + ch,
                 gB + (size_t)row * gstride + (size_t)c * 64 + ch);
        }
        CP_COMMIT();
    };

    issue(0); issue(1); issue(2);

    for (int c = 0; c < nch; c++) {
        CP_WAIT(2);
        __syncthreads();
        if (c + 3 < nch) issue(c + 3);

        const uint32_t sA = sb0 + (c & (NSTAGE - 1)) * STAGE16;
        const uint32_t sB = sA + TILE_SM;

#pragma unroll
        for (int ks = 0; ks < 2; ks++) {
            const uint32_t akb = ks * 32 + (lane >> 4) * 16;
            const uint32_t bkb = ks * 32 + ((lane >> 3) & 1) * 16;

            uint32_t af[2][4];
#pragma unroll
            for (int am = 0; am < 2; am++) {
                uint32_t ro = (uint32_t)(wm * 32 + am * 16 + (lane & 15)) * ROWB + akb;
                ldsm4(af[am][0], af[am][1], af[am][2], af[am][3], sA + ro);
            }
            uint32_t bf[8][2];
#pragma unroll
            for (int bp = 0; bp < 4; bp++) {
                uint32_t ro = (uint32_t)(wn * 64 + bp * 16 + (lane >> 4) * 8 + (lane & 7)) * ROWB + bkb;
                ldsm4(bf[2*bp][0], bf[2*bp][1], bf[2*bp+1][0], bf[2*bp+1][1], sB + ro);
            }
#pragma unroll
            for (int am = 0; am < 2; am++)
#pragma unroll
                for (int bn = 0; bn < 8; bn++)
                    mma_fp16(acc[am][bn], af[am], bf[bn]);
        }
        __syncthreads();
    }

#pragma unroll
    for (int am = 0; am < 2; am++) {
        int r0 = rowBlk + wm * 32 + am * 16 + (lane >> 2);
#pragma unroll
        for (int bn = 0; bn < 8; bn++) {
            int col = colBlk + wn * 64 + bn * 8 + (lane & 3) * 2;
            float2 v0 = {acc[am][bn][0], acc[am][bn][1]};
            float2 v1 = {acc[am][bn][2], acc[am][bn][3]};
            *(float2*)(C + (size_t)r0 * N + col)       = v0;
            *(float2*)(C + (size_t)(r0 + 8) * N + col) = v1;
        }
    }
}

// ---------------------------------------------------------------------------
// RoPE cos/sin table (double precision -> fp32)
// ---------------------------------------------------------------------------
__global__ void rope_table(float* __restrict__ cost, float* __restrict__ sint)
{
    int idx = blockIdx.x * blockDim.x + threadIdx.x;
    if (idx >= S_LEN * 64) return;
    int i = idx & 63;
    int s = idx >> 6;
    double freq = pow(10000.0, -2.0 * i / 128.0);
    double sa, ca;
    sincos((double)s * freq, &sa, &ca);
    cost[idx] = (float)ca;
    sint[idx] = (float)sa;
}

// ---------------------------------------------------------------------------
// RoPE + split into head-major bf16 hi/lo arrays (Q,K rotated; V split only)
// ---------------------------------------------------------------------------
__global__ void rope_split(const float* __restrict__ qkv,
                           const float* __restrict__ cost, const float* __restrict__ sint,
                           __nv_bfloat16* __restrict__ qh, __nv_bfloat16* __restrict__ ql,
                           __nv_bfloat16* __restrict__ kh, __nv_bfloat16* __restrict__ kl,
                           __nv_bfloat16* __restrict__ vh, __nv_bfloat16* __restrict__ vl)
{
    int idx = blockIdx.x * blockDim.x + threadIdx.x;
    const int total = S_LEN * 48 * 64;
    if (idx >= total) return;
    int i = idx & 63;
    int h = (idx >> 6) % 48;
    int s = idx / (64 * 48);

    auto wsplit = [](float v, __nv_bfloat16* hi, __nv_bfloat16* lo, size_t d) {
        __nv_bfloat16 hv = __float2bfloat16_rn(v);
        hi[d] = hv;
        lo[d] = __float2bfloat16_rn(v - __bfloat162float(hv));
    };

    if (h < 40) {
        const float* src; __nv_bfloat16 *dh, *dl; size_t d;
        if (h < NUM_HEADS) {
            src = qkv + (size_t)s * QKV_OUT + h * HEAD_DIM;
            dh = qh; dl = ql;
            d = ((size_t)h * S_LEN + s) * HEAD_DIM + i;
        } else {
            int hk = h - NUM_HEADS;
            src = qkv + (size_t)s * QKV_OUT + Q_SIZE + hk * HEAD_DIM;
            dh = kh; dl = kl;
            d = ((size_t)hk * S_LEN + s) * HEAD_DIM + i;
        }
        float x1 = src[i], x2 = src[i + 64];
        float c = cost[s * 64 + i], sn = sint[s * 64 + i];
        wsplit(x1 * c - x2 * sn, dh, dl, d);
        wsplit(x1 * sn + x2 * c, dh, dl, d + 64);
    } else {
        int hv = h - 40;
        const float* src = qkv + (size_t)s * QKV_OUT + Q_SIZE + KV_SIZE + hv * HEAD_DIM;
        size_t d = ((size_t)hv * S_LEN + s) * HEAD_DIM + i;
        wsplit(src[i], vh, vl, d);
        wsplit(src[i + 64], vh, vl, d + 64);
    }
}

// ---------------------------------------------------------------------------
// Tensor-core flash attention (causal, GQA), split-bf16 x3 for S and PV.
// Block = 64 q-rows x 1 head, 4 warps. Output: plain fp16 (feeds O-proj).
// ---------------------------------------------------------------------------
#define FP  272
#define FT  (64 * FP)
#define FLASH_SMEM (6 * FT)

__global__ __launch_bounds__(128, 2) void flash_mma(
    const __nv_bfloat16* __restrict__ qh_g, const __nv_bfloat16* __restrict__ ql_g,
    const __nv_bfloat16* __restrict__ kh_g, const __nv_bfloat16* __restrict__ kl_g,
    const __nv_bfloat16* __restrict__ vh_g, const __nv_bfloat16* __restrict__ vl_g,
    __half* __restrict__ out_h)
{
    extern __shared__ __align__(128) char sm[];
    const uint32_t Qh = smem_u32(sm);
    const uint32_t Ql = Qh + FT;
    const uint32_t Kh = Qh + 2 * FT;
    const uint32_t Kl = Qh + 3 * FT;
    const uint32_t Vh = Qh + 4 * FT;
    const uint32_t Vl = Qh + 5 * FT;

    const int tid  = threadIdx.x;
    const int lane = tid & 31;
    const int w    = tid >> 5;
    const int qt   = gridDim.x - 1 - blockIdx.x;
    const int q0   = qt * 64;
    const int head = blockIdx.y;
    const int kvh  = head >> 2;
    const float scale = 0.088388347648318447f;

    {
        const char* sh = (const char*)(qh_g + ((size_t)head * S_LEN + q0) * HEAD_DIM);
        const char* sl = (const char*)(ql_g + ((size_t)head * S_LEN + q0) * HEAD_DIM);
#pragma unroll
        for (int i = 0; i < 8; i++) {
            int e = tid + i * 128;
            int r = e >> 4, ch = (e & 15) * 16;
            cp16(Qh + r * FP + ch, sh + (size_t)r * 256 + ch);
            cp16(Ql + r * FP + ch, sl + (size_t)r * 256 + ch);
        }
        CP_COMMIT(); CP_WAIT(0);
    }
    __syncthreads();

    float o[16][4];
#pragma unroll
    for (int d = 0; d < 16; d++)
#pragma unroll
        for (int c = 0; c < 4; c++) o[d][c] = 0.0f;
    float m_lo = -1e30f, m_hi = -1e30f, l_lo = 0.0f, l_hi = 0.0f;

    const int gi_lo = q0 + w * 16 + (lane >> 2);
    const int gi_hi = gi_lo + 8;

    const char* kh_src = (const char*)(kh_g + (size_t)kvh * S_LEN * HEAD_DIM);
    const char* kl_src = (const char*)(kl_g + (size_t)kvh * S_LEN * HEAD_DIM);
    const char* vh_src = (const char*)(vh_g + (size_t)kvh * S_LEN * HEAD_DIM);
    const char* vl_src = (const char*)(vl_g + (size_t)kvh * S_LEN * HEAD_DIM);

    const int ntiles = qt + 1;
    for (int t = 0; t < ntiles; t++) {
        const int j0 = t * 64;
#pragma unroll
        for (int i = 0; i < 8; i++) {
            int e = tid + i * 128;
            int r = e >> 4, ch = (e & 15) * 16;
            size_t so = (size_t)(j0 + r) * 256 + ch;
            uint32_t dof = r * FP + ch;
            cp16(Kh + dof, kh_src + so);
            cp16(Kl + dof, kl_src + so);
            cp16(Vh + dof, vh_src + so);
            cp16(Vl + dof, vl_src + so);
        }
        CP_COMMIT(); CP_WAIT(0);
        __syncthreads();

        float sacc[8][4];
#pragma unroll
        for (int bn = 0; bn < 8; bn++)
#pragma unroll
            for (int c = 0; c < 4; c++) sacc[bn][c] = 0.0f;

#pragma unroll
        for (int ks = 0; ks < 8; ks++) {
            uint32_t aoff = (uint32_t)(w * 16 + (lane & 15)) * FP + ks * 32 + (lane >> 4) * 16;
            uint32_t a_h[4], a_l[4];
            ldsm4(a_h[0], a_h[1], a_h[2], a_h[3], Qh + aoff);
            ldsm4(a_l[0], a_l[1], a_l[2], a_l[3], Ql + aoff);
#pragma unroll
            for (int bp = 0; bp < 4; bp++) {
                uint32_t koff = (uint32_t)(bp * 16 + (lane >> 4) * 8 + (lane & 7)) * FP
                              + ks * 32 + ((lane >> 3) & 1) * 16;
                uint32_t bh[4], bl[4];
                ldsm4(bh[0], bh[1], bh[2], bh[3], Kh + koff);
                ldsm4(bl[0], bl[1], bl[2], bl[3], Kl + koff);
                mma_bf16(sacc[2*bp],   a_h, &bh[0]);
                mma_bf16(sacc[2*bp],   a_h, &bl[0]);
                mma_bf16(sacc[2*bp],   a_l, &bh[0]);
                mma_bf16(sacc[2*bp+1], a_h, &bh[2]);
                mma_bf16(sacc[2*bp+1], a_h, &bl[2]);
                mma_bf16(sacc[2*bp+1], a_l, &bh[2]);
            }
        }

        const bool need_mask = (j0 == q0);
        float mx0 = m_lo, mx1 = m_hi;
#pragma unroll
        for (int bn = 0; bn < 8; bn++) {
            int gj = j0 + bn * 8 + (lane & 3) * 2;
            float s0 = sacc[bn][0] * scale, s1 = sacc[bn][1] * scale;
            float s2 = sacc[bn][2] * scale, s3 = sacc[bn][3] * scale;
            if (need_mask) {
                if (gj     > gi_lo) s0 = -1e30f;
                if (gj + 1 > gi_lo) s1 = -1e30f;
                if (gj     > gi_hi) s2 = -1e30f;
                if (gj + 1 > gi_hi) s3 = -1e30f;
            }
            sacc[bn][0] = s0; sacc[bn][1] = s1; sacc[bn][2] = s2; sacc[bn][3] = s3;
            mx0 = fmaxf(mx0, fmaxf(s0, s1));
            mx1 = fmaxf(mx1, fmaxf(s2, s3));
        }
        mx0 = fmaxf(mx0, __shfl_xor_sync(0xffffffffu, mx0, 1));
        mx0 = fmaxf(mx0, __shfl_xor_sync(0xffffffffu, mx0, 2));
        mx1 = fmaxf(mx1, __shfl_xor_sync(0xffffffffu, mx1, 1));
        mx1 = fmaxf(mx1, __shfl_xor_sync(0xffffffffu, mx1, 2));

        float alpha0 = __expf(m_lo - mx0);
        float alpha1 = __expf(m_hi - mx1);
        float sum0 = 0.0f, sum1 = 0.0f;
#pragma unroll
        for (int bn = 0; bn < 8; bn++) {
            float p0 = __expf(sacc[bn][0] - mx0);
            float p1 = __expf(sacc[bn][1] - mx0);
            float p2 = __expf(sacc[bn][2] - mx1);
            float p3 = __expf(sacc[bn][3] - mx1);
            sacc[bn][0] = p0; sacc[bn][1] = p1; sacc[bn][2] = p2; sacc[bn][3] = p3;
            sum0 += p0 + p1; sum1 += p2 + p3;
        }
        sum0 += __shfl_xor_sync(0xffffffffu, sum0, 1);
        sum0 += __shfl_xor_sync(0xffffffffu, sum0, 2);
        sum1 += __shfl_xor_sync(0xffffffffu, sum1, 1);
        sum1 += __shfl_xor_sync(0xffffffffu, sum1, 2);
        l_lo = l_lo * alpha0 + sum0;
        l_hi = l_hi * alpha1 + sum1;
        m_lo = mx0; m_hi = mx1;
#pragma unroll
        for (int d = 0; d < 16; d++) {
            o[d][0] *= alpha0; o[d][1] *= alpha0;
            o[d][2] *= alpha1; o[d][3] *= alpha1;
        }

#pragma unroll
        for (int ks2 = 0; ks2 < 4; ks2++) {
            uint32_t ah[4], al[4];
            split2(sacc[2*ks2][0],   sacc[2*ks2][1],   ah[0], al[0]);
            split2(sacc[2*ks2][2],   sacc[2*ks2][3],   ah[1], al[1]);
            split2(sacc[2*ks2+1][0], sacc[2*ks2+1][1], ah[2], al[2]);
            split2(sacc[2*ks2+1][2], sacc[2*ks2+1][3], ah[3], al[3]);
#pragma unroll
            for (int vp = 0; vp < 8; vp++) {
                uint32_t voff = (uint32_t)(ks2 * 16 + ((lane >> 3) & 1) * 8 + (lane & 7)) * FP
                              + (vp * 16 + (lane >> 4) * 8) * 2;
                uint32_t bh[4], bl[4];
                ldsm4t(bh[0], bh[1], bh[2], bh[3], Vh + voff);
                ldsm4t(bl[0], bl[1], bl[2], bl[3], Vl + voff);
                mma_bf16(o[2*vp],   ah, &bh[0]);
                mma_bf16(o[2*vp],   ah, &bl[0]);
                mma_bf16(o[2*vp],   al, &bh[0]);
                mma_bf16(o[2*vp+1], ah, &bh[2]);
                mma_bf16(o[2*vp+1], ah, &bl[2]);
                mma_bf16(o[2*vp+1], al, &bh[2]);
            }
        }
        __syncthreads();
    }

    // ---- epilogue: normalize, write plain fp16
    float inv0 = 1.0f / l_lo, inv1 = 1.0f / l_hi;
    size_t base0 = (size_t)gi_lo * Q_SIZE + head * HEAD_DIM + (lane & 3) * 2;
    size_t base1 = base0 + (size_t)8 * Q_SIZE;
#pragma unroll
    for (int d = 0; d < 16; d++) {
        *(__half2*)(out_h + base0 + d * 8) = __floats2half2_rn(o[d][0] * inv0, o[d][1] * inv0);
        *(__half2*)(out_h + base1 + d * 8) = __floats2half2_rn(o[d][2] * inv1, o[d][3] * inv1);
    }
}

// ---------------------------------------------------------------------------
// Launch
// ---------------------------------------------------------------------------
extern "C" void kernel_launch(void* const* d_in, const int* in_sizes, int n_in,
                              void* d_out, int out_size)
{
    const float* hidden = (const float*)d_in[0];
    const float* w_qkv  = (const float*)d_in[1];
    const float* w_o    = (const float*)d_in[2];
    float* out = (float*)d_out;

    float *qkv, *cost, *sint;
    __half *hidh, *wqkvh, *woh, *attnh;
    __nv_bfloat16 *qh, *ql, *kh, *kl, *vh, *vl;
    cudaGetSymbolAddress((void**)&qkv, g_qkv);
    cudaGetSymbolAddress((void**)&cost, g_cos);
    cudaGetSymbolAddress((void**)&sint, g_sin);
    cudaGetSymbolAddress((void**)&hidh, g_hid_h);
    cudaGetSymbolAddress((void**)&wqkvh, g_wqkv_h);
    cudaGetSymbolAddress((void**)&woh, g_wo_h);
    cudaGetSymbolAddress((void**)&attnh, g_attn_h);
    cudaGetSymbolAddress((void**)&qh, g_q_hi);
    cudaGetSymbolAddress((void**)&ql, g_q_lo);
    cudaGetSymbolAddress((void**)&kh, g_k_hi);
    cudaGetSymbolAddress((void**)&kl, g_k_lo);
    cudaGetSymbolAddress((void**)&vh, g_v_hi);
    cudaGetSymbolAddress((void**)&vl, g_v_lo);

    cudaFuncSetAttribute(gemm_fp16, cudaFuncAttributeMaxDynamicSharedMemorySize, GEMM_SMEM);
    cudaFuncSetAttribute(flash_mma, cudaFuncAttributeMaxDynamicSharedMemorySize, FLASH_SMEM);

    // 0. RoPE table + fp16 input conversion
    rope_table<<<(S_LEN * 64 + 255) / 256, 256>>>(cost, sint);
    {
        int n1 = S_LEN * HIDDEN;
        cvt_fp16<<<n1 / 4 / 256, 256>>>(hidden, hidh, n1);
        int n2 = QKV_OUT * HIDDEN;
        cvt_fp16<<<n2 / 4 / 256, 256>>>(w_qkv, wqkvh, n2);
        int n3 = HIDDEN * HIDDEN;
        cvt_fp16<<<n3 / 4 / 256, 256>>>(w_o, woh, n3);
    }
    // 1. QKV projection (fp16 tensor cores)
    gemm_fp16<<<dim3(QKV_OUT / 128, S_LEN / 128), 256, GEMM_SMEM>>>(
        hidh, wqkvh, qkv, S_LEN, QKV_OUT, HIDDEN);
    // 2. RoPE + head-major split bf16
    {
        int total = S_LEN * 48 * 64;
        rope_split<<<(total + 255) / 256, 256>>>(qkv, cost, sint,
                                                 qh, ql, kh, kl, vh, vl);
    }
    // 3. Tensor-core flash attention -> fp16 output
    flash_mma<<<dim3(S_LEN / 64, NUM_HEADS), 128, FLASH_SMEM>>>(
        qh, ql, kh, kl, vh, vl, attnh);
    // 4. Output projection (fp16 tensor cores)
    gemm_fp16<<<dim3(HIDDEN / 128, S_LEN / 128), 256, GEMM_SMEM>>>(
        attnh, woh, out, S_LEN, HIDDEN, HIDDEN);
}

// round 8
// speedup vs baseline: 7.4302x; 1.0890x over previous
#include <cuda_runtime.h>
#include <cuda_bf16.h>
#include <cuda_fp16.h>
#include <math.h>
#include <stdint.h>

// ---------------------------------------------------------------------------
// Problem constants
// ---------------------------------------------------------------------------
#define S_LEN     2048
#define HIDDEN    4096
#define NUM_HEADS 32
#define NUM_KVH   8
#define HEAD_DIM  128
#define Q_SIZE    (NUM_HEADS * HEAD_DIM)       // 4096
#define KV_SIZE   (NUM_KVH * HEAD_DIM)         // 1024
#define QKV_OUT   (Q_SIZE + 2 * KV_SIZE)       // 6144

// Scratch (device globals; no allocations allowed)
__device__ float         g_qkv[S_LEN * QKV_OUT];
__device__ __half        g_hid_h[S_LEN * HIDDEN];
__device__ __half        g_wqkv_h[QKV_OUT * HIDDEN];
__device__ __half        g_wo_h[HIDDEN * HIDDEN];
__device__ __half        g_attn_h[S_LEN * Q_SIZE];
// RoPE'd, head-major, split bf16 Q/K/V for the flash kernel
__device__ __nv_bfloat16 g_q_hi[NUM_HEADS * S_LEN * HEAD_DIM];
__device__ __nv_bfloat16 g_q_lo[NUM_HEADS * S_LEN * HEAD_DIM];
__device__ __nv_bfloat16 g_k_hi[NUM_KVH * S_LEN * HEAD_DIM];
__device__ __nv_bfloat16 g_k_lo[NUM_KVH * S_LEN * HEAD_DIM];
__device__ __nv_bfloat16 g_v_hi[NUM_KVH * S_LEN * HEAD_DIM];
__device__ __nv_bfloat16 g_v_lo[NUM_KVH * S_LEN * HEAD_DIM];
__device__ float         g_cos[S_LEN * 64];
__device__ float         g_sin[S_LEN * 64];

// ---------------------------------------------------------------------------
// PTX helpers (base sm_103 compatible)
// ---------------------------------------------------------------------------
__device__ __forceinline__ uint32_t smem_u32(const void* p) {
    uint32_t a;
    asm("{ .reg .u64 t; cvta.to.shared.u64 t, %1; cvt.u32.u64 %0, t; }"
        : "=r"(a) : "l"(p));
    return a;
}
__device__ __forceinline__ void cp16(uint32_t dst, const void* src) {
    asm volatile("cp.async.cg.shared.global [%0], [%1], 16;"
                 :: "r"(dst), "l"(src));
}
#define CP_COMMIT()  asm volatile("cp.async.commit_group;" ::: "memory")
#define CP_WAIT(n)   asm volatile("cp.async.wait_group %0;" :: "n"(n) : "memory")

__device__ __forceinline__ void ldsm4(uint32_t& r0, uint32_t& r1,
                                      uint32_t& r2, uint32_t& r3, uint32_t addr) {
    asm volatile("ldmatrix.sync.aligned.m8n8.x4.shared.b16 {%0,%1,%2,%3}, [%4];"
                 : "=r"(r0), "=r"(r1), "=r"(r2), "=r"(r3) : "r"(addr));
}
__device__ __forceinline__ void ldsm4t(uint32_t& r0, uint32_t& r1,
                                       uint32_t& r2, uint32_t& r3, uint32_t addr) {
    asm volatile("ldmatrix.sync.aligned.m8n8.x4.trans.shared.b16 {%0,%1,%2,%3}, [%4];"
                 : "=r"(r0), "=r"(r1), "=r"(r2), "=r"(r3) : "r"(addr));
}
__device__ __forceinline__ void mma_bf16(float* d, const uint32_t* a, const uint32_t* b) {
    asm volatile(
        "mma.sync.aligned.m16n8k16.row.col.f32.bf16.bf16.f32 "
        "{%0,%1,%2,%3},{%4,%5,%6,%7},{%8,%9},{%0,%1,%2,%3};"
        : "+f"(d[0]), "+f"(d[1]), "+f"(d[2]), "+f"(d[3])
        : "r"(a[0]), "r"(a[1]), "r"(a[2]), "r"(a[3]), "r"(b[0]), "r"(b[1]));
}
__device__ __forceinline__ void mma_fp16(float* d, const uint32_t* a, const uint32_t* b) {
    asm volatile(
        "mma.sync.aligned.m16n8k16.row.col.f32.f16.f16.f32 "
        "{%0,%1,%2,%3},{%4,%5,%6,%7},{%8,%9},{%0,%1,%2,%3};"
        : "+f"(d[0]), "+f"(d[1]), "+f"(d[2]), "+f"(d[3])
        : "r"(a[0]), "r"(a[1]), "r"(a[2]), "r"(a[3]), "r"(b[0]), "r"(b[1]));
}
__device__ __forceinline__ uint32_t packbf(__nv_bfloat16 a, __nv_bfloat16 b) {
    return ((uint32_t)__bfloat16_as_ushort(b) << 16) | __bfloat16_as_ushort(a);
}
__device__ __forceinline__ void split2(float a, float b, uint32_t& hi, uint32_t& lo) {
    __nv_bfloat16 ha = __float2bfloat16_rn(a), hb = __float2bfloat16_rn(b);
    __nv_bfloat16 la = __float2bfloat16_rn(a - __bfloat162float(ha));
    __nv_bfloat16 lb = __float2bfloat16_rn(b - __bfloat162float(hb));
    hi = packbf(ha, hb); lo = packbf(la, lb);
}

// ---------------------------------------------------------------------------
// fp32 -> fp16 convert (8 floats / thread)
// ---------------------------------------------------------------------------
__global__ void cvt_fp16(const float* __restrict__ x, __half* __restrict__ y, int n)
{
    int i = (blockIdx.x * blockDim.x + threadIdx.x) * 8;
    if (i >= n) return;
    float4 v0 = *(const float4*)(x + i);
    float4 v1 = *(const float4*)(x + i + 4);
    __half2 h0 = __floats2half2_rn(v0.x, v0.y);
    __half2 h1 = __floats2half2_rn(v0.z, v0.w);
    __half2 h2 = __floats2half2_rn(v1.x, v1.y);
    __half2 h3 = __floats2half2_rn(v1.z, v1.w);
    uint4 pk;
    pk.x = *(uint32_t*)&h0; pk.y = *(uint32_t*)&h1;
    pk.z = *(uint32_t*)&h2; pk.w = *(uint32_t*)&h3;
    *(uint4*)(y + i) = pk;
}

// ---------------------------------------------------------------------------
// fp16 warp-MMA GEMM: C[M,N] = A[M,K] * B[N,K]^T
// 128x128 CTA tile, 8 warps (4M x 2N), warp 32x64, K-chunk 64, 2-stage pipe.
// ---------------------------------------------------------------------------
#define ROWB       144                      // 128B data + 16B pad (conflict-free)
#define TILE_SM    (128 * ROWB)             // 18432 B
#define STAGE16    (2 * TILE_SM)            // A + B = 36864 B
#define GEMM_SMEM  (2 * STAGE16)            // 73728 B

__global__ __launch_bounds__(256, 2) void gemm_fp16(
    const __half* __restrict__ A, const __half* __restrict__ B,
    float* __restrict__ C, int M, int N, int K)
{
    extern __shared__ __align__(128) char smem[];
    const uint32_t sb0 = smem_u32(smem);
    const int tid  = threadIdx.x;
    const int lane = tid & 31;
    const int wid  = tid >> 5;
    const int wm   = wid & 3;
    const int wn   = wid >> 2;
    const int rowBlk = blockIdx.y * 128;
    const int colBlk = blockIdx.x * 128;

    const size_t gstride = (size_t)K * 2;
    const char* gA = (const char*)(A + (size_t)rowBlk * K);
    const char* gB = (const char*)(B + (size_t)colBlk * K);

    float acc[2][8][4];
#pragma unroll
    for (int i = 0; i < 2; i++)
#pragma unroll
        for (int j = 0; j < 8; j++)
#pragma unroll
            for (int k = 0; k < 4; k++) acc[i][j][k] = 0.0f;

    const int nch = K / 64;

    auto issue = [&](int c) {
        const uint32_t stg = sb0 + (c & 1) * STAGE16;
#pragma unroll
        for (int u = 0; u < 4; u++) {
            int e   = tid + u * 256;          // 0..1023
            int row = e >> 3;
            int ch  = (e & 7) * 16;
            cp16(stg + row * ROWB + ch,
                 gA + (size_t)row * gstride + (size_t)c * 128 + ch);
            cp16(stg + TILE_SM + row * ROWB + ch,
                 gB + (size_t)row * gstride + (size_t)c * 128 + ch);
        }
        CP_COMMIT();
    };

    issue(0);

    for (int c = 0; c < nch; c++) {
        if (c + 1 < nch) { issue(c + 1); CP_WAIT(1); }
        else             { CP_WAIT(0); }
        __syncthreads();

        const uint32_t sA = sb0 + (c & 1) * STAGE16;
        const uint32_t sB = sA + TILE_SM;

#pragma unroll
        for (int ks = 0; ks < 4; ks++) {
            const uint32_t akb = ks * 32 + (lane >> 4) * 16;
            const uint32_t bkb = ks * 32 + ((lane >> 3) & 1) * 16;

            uint32_t af[2][4];
#pragma unroll
            for (int am = 0; am < 2; am++) {
                uint32_t ro = (uint32_t)(wm * 32 + am * 16 + (lane & 15)) * ROWB + akb;
                ldsm4(af[am][0], af[am][1], af[am][2], af[am][3], sA + ro);
            }
            uint32_t bf[8][2];
#pragma unroll
            for (int bp = 0; bp < 4; bp++) {
                uint32_t ro = (uint32_t)(wn * 64 + bp * 16 + (lane >> 4) * 8 + (lane & 7)) * ROWB + bkb;
                ldsm4(bf[2*bp][0], bf[2*bp][1], bf[2*bp+1][0], bf[2*bp+1][1], sB + ro);
            }
#pragma unroll
            for (int am = 0; am < 2; am++)
#pragma unroll
                for (int bn = 0; bn < 8; bn++)
                    mma_fp16(acc[am][bn], af[am], bf[bn]);
        }
        __syncthreads();
    }

#pragma unroll
    for (int am = 0; am < 2; am++) {
        int r0 = rowBlk + wm * 32 + am * 16 + (lane >> 2);
#pragma unroll
        for (int bn = 0; bn < 8; bn++) {
            int col = colBlk + wn * 64 + bn * 8 + (lane & 3) * 2;
            float2 v0 = {acc[am][bn][0], acc[am][bn][1]};
            float2 v1 = {acc[am][bn][2], acc[am][bn][3]};
            *(float2*)(C + (size_t)r0 * N + col)       = v0;
            *(float2*)(C + (size_t)(r0 + 8) * N + col) = v1;
        }
    }
}

// ---------------------------------------------------------------------------
// RoPE cos/sin table (double precision -> fp32)
// ---------------------------------------------------------------------------
__global__ void rope_table(float* __restrict__ cost, float* __restrict__ sint)
{
    int idx = blockIdx.x * blockDim.x + threadIdx.x;
    if (idx >= S_LEN * 64) return;
    int i = idx & 63;
    int s = idx >> 6;
    double freq = pow(10000.0, -2.0 * i / 128.0);
    double sa, ca;
    sincos((double)s * freq, &sa, &ca);
    cost[idx] = (float)ca;
    sint[idx] = (float)sa;
}

// ---------------------------------------------------------------------------
// RoPE + split into head-major bf16 hi/lo arrays (Q,K rotated; V split only)
// ---------------------------------------------------------------------------
__global__ void rope_split(const float* __restrict__ qkv,
                           const float* __restrict__ cost, const float* __restrict__ sint,
                           __nv_bfloat16* __restrict__ qh, __nv_bfloat16* __restrict__ ql,
                           __nv_bfloat16* __restrict__ kh, __nv_bfloat16* __restrict__ kl,
                           __nv_bfloat16* __restrict__ vh, __nv_bfloat16* __restrict__ vl)
{
    int idx = blockIdx.x * blockDim.x + threadIdx.x;
    const int total = S_LEN * 48 * 64;
    if (idx >= total) return;
    int i = idx & 63;
    int h = (idx >> 6) % 48;
    int s = idx / (64 * 48);

    auto wsplit = [](float v, __nv_bfloat16* hi, __nv_bfloat16* lo, size_t d) {
        __nv_bfloat16 hv = __float2bfloat16_rn(v);
        hi[d] = hv;
        lo[d] = __float2bfloat16_rn(v - __bfloat162float(hv));
    };

    if (h < 40) {
        const float* src; __nv_bfloat16 *dh, *dl; size_t d;
        if (h < NUM_HEADS) {
            src = qkv + (size_t)s * QKV_OUT + h * HEAD_DIM;
            dh = qh; dl = ql;
            d = ((size_t)h * S_LEN + s) * HEAD_DIM + i;
        } else {
            int hk = h - NUM_HEADS;
            src = qkv + (size_t)s * QKV_OUT + Q_SIZE + hk * HEAD_DIM;
            dh = kh; dl = kl;
            d = ((size_t)hk * S_LEN + s) * HEAD_DIM + i;
        }
        float x1 = src[i], x2 = src[i + 64];
        float c = cost[s * 64 + i], sn = sint[s * 64 + i];
        wsplit(x1 * c - x2 * sn, dh, dl, d);
        wsplit(x1 * sn + x2 * c, dh, dl, d + 64);
    } else {
        int hv = h - 40;
        const float* src = qkv + (size_t)s * QKV_OUT + Q_SIZE + KV_SIZE + hv * HEAD_DIM;
        size_t d = ((size_t)hv * S_LEN + s) * HEAD_DIM + i;
        wsplit(src[i], vh, vl, d);
        wsplit(src[i + 64], vh, vl, d + 64);
    }
}

// ---------------------------------------------------------------------------
// Tensor-core flash attention (causal, GQA), split-bf16 x3 for S and PV.
// Block = 64 q-rows x 1 head, 4 warps. Software-pipelined K/V loads:
//   wait K -> QK -> prefetch K(t+1) -> softmax -> wait V -> PV -> prefetch V(t+1)
// ---------------------------------------------------------------------------
#define FP  272
#define FT  (64 * FP)
#define FLASH_SMEM (6 * FT)

__global__ __launch_bounds__(128, 2) void flash_mma(
    const __nv_bfloat16* __restrict__ qh_g, const __nv_bfloat16* __restrict__ ql_g,
    const __nv_bfloat16* __restrict__ kh_g, const __nv_bfloat16* __restrict__ kl_g,
    const __nv_bfloat16* __restrict__ vh_g, const __nv_bfloat16* __restrict__ vl_g,
    __half* __restrict__ out_h)
{
    extern __shared__ __align__(128) char sm[];
    const uint32_t Qh = smem_u32(sm);
    const uint32_t Ql = Qh + FT;
    const uint32_t Kh = Qh + 2 * FT;
    const uint32_t Kl = Qh + 3 * FT;
    const uint32_t Vh = Qh + 4 * FT;
    const uint32_t Vl = Qh + 5 * FT;

    const int tid  = threadIdx.x;
    const int lane = tid & 31;
    const int w    = tid >> 5;
    const int qt   = gridDim.x - 1 - blockIdx.x;
    const int q0   = qt * 64;
    const int head = blockIdx.y;
    const int kvh  = head >> 2;
    const float scale = 0.088388347648318447f;

    const char* kh_src = (const char*)(kh_g + (size_t)kvh * S_LEN * HEAD_DIM);
    const char* kl_src = (const char*)(kl_g + (size_t)kvh * S_LEN * HEAD_DIM);
    const char* vh_src = (const char*)(vh_g + (size_t)kvh * S_LEN * HEAD_DIM);
    const char* vl_src = (const char*)(vl_g + (size_t)kvh * S_LEN * HEAD_DIM);

    auto issueK = [&](int j0) {
#pragma unroll
        for (int i = 0; i < 8; i++) {
            int e = tid + i * 128;
            int r = e >> 4, ch = (e & 15) * 16;
            size_t so = (size_t)(j0 + r) * 256 + ch;
            uint32_t dof = (uint32_t)(r * FP + ch);
            cp16(Kh + dof, kh_src + so);
            cp16(Kl + dof, kl_src + so);
        }
        CP_COMMIT();
    };
    auto issueV = [&](int j0) {
#pragma unroll
        for (int i = 0; i < 8; i++) {
            int e = tid + i * 128;
            int r = e >> 4, ch = (e & 15) * 16;
            size_t so = (size_t)(j0 + r) * 256 + ch;
            uint32_t dof = (uint32_t)(r * FP + ch);
            cp16(Vh + dof, vh_src + so);
            cp16(Vl + dof, vl_src + so);
        }
        CP_COMMIT();
    };

    // ---- prologue: Q load + first K/V tiles in flight
    {
        const char* sh = (const char*)(qh_g + ((size_t)head * S_LEN + q0) * HEAD_DIM);
        const char* sl = (const char*)(ql_g + ((size_t)head * S_LEN + q0) * HEAD_DIM);
#pragma unroll
        for (int i = 0; i < 8; i++) {
            int e = tid + i * 128;
            int r = e >> 4, ch = (e & 15) * 16;
            cp16(Qh + r * FP + ch, sh + (size_t)r * 256 + ch);
            cp16(Ql + r * FP + ch, sl + (size_t)r * 256 + ch);
        }
        CP_COMMIT();
    }
    issueK(0);
    issueV(0);
    CP_WAIT(2);       // Q ready; K0/V0 still in flight
    __syncthreads();

    float o[16][4];
#pragma unroll
    for (int d = 0; d < 16; d++)
#pragma unroll
        for (int c = 0; c < 4; c++) o[d][c] = 0.0f;
    float m_lo = -1e30f, m_hi = -1e30f, l_lo = 0.0f, l_hi = 0.0f;

    const int gi_lo = q0 + w * 16 + (lane >> 2);
    const int gi_hi = gi_lo + 8;

    const int ntiles = qt + 1;
    for (int t = 0; t < ntiles; t++) {
        const int j0 = t * 64;
        const bool more = (t + 1 < ntiles);

        // K(t) ready (V(t) may still be in flight)
        CP_WAIT(1);
        __syncthreads();

        // ---- S = Q K^T (3-term split)
        float sacc[8][4];
#pragma unroll
        for (int bn = 0; bn < 8; bn++)
#pragma unroll
            for (int c = 0; c < 4; c++) sacc[bn][c] = 0.0f;

#pragma unroll
        for (int ks = 0; ks < 8; ks++) {
            uint32_t aoff = (uint32_t)(w * 16 + (lane & 15)) * FP + ks * 32 + (lane >> 4) * 16;
            uint32_t a_h[4], a_l[4];
            ldsm4(a_h[0], a_h[1], a_h[2], a_h[3], Qh + aoff);
            ldsm4(a_l[0], a_l[1], a_l[2], a_l[3], Ql + aoff);
#pragma unroll
            for (int bp = 0; bp < 4; bp++) {
                uint32_t koff = (uint32_t)(bp * 16 + (lane >> 4) * 8 + (lane & 7)) * FP
                              + ks * 32 + ((lane >> 3) & 1) * 16;
                uint32_t bh[4], bl[4];
                ldsm4(bh[0], bh[1], bh[2], bh[3], Kh + koff);
                ldsm4(bl[0], bl[1], bl[2], bl[3], Kl + koff);
                mma_bf16(sacc[2*bp],   a_h, &bh[0]);
                mma_bf16(sacc[2*bp],   a_h, &bl[0]);
                mma_bf16(sacc[2*bp],   a_l, &bh[0]);
                mma_bf16(sacc[2*bp+1], a_h, &bh[2]);
                mma_bf16(sacc[2*bp+1], a_h, &bl[2]);
                mma_bf16(sacc[2*bp+1], a_l, &bh[2]);
            }
        }
        __syncthreads();                 // all warps done reading K smem
        if (more) issueK(j0 + 64);       // prefetch next K over softmax+PV

        // ---- masked online softmax (registers only)
        const bool need_mask = (j0 == q0);
        float mx0 = m_lo, mx1 = m_hi;
#pragma unroll
        for (int bn = 0; bn < 8; bn++) {
            int gj = j0 + bn * 8 + (lane & 3) * 2;
            float s0 = sacc[bn][0] * scale, s1 = sacc[bn][1] * scale;
            float s2 = sacc[bn][2] * scale, s3 = sacc[bn][3] * scale;
            if (need_mask) {
                if (gj     > gi_lo) s0 = -1e30f;
                if (gj + 1 > gi_lo) s1 = -1e30f;
                if (gj     > gi_hi) s2 = -1e30f;
                if (gj + 1 > gi_hi) s3 = -1e30f;
            }
            sacc[bn][0] = s0; sacc[bn][1] = s1; sacc[bn][2] = s2; sacc[bn][3] = s3;
            mx0 = fmaxf(mx0, fmaxf(s0, s1));
            mx1 = fmaxf(mx1, fmaxf(s2, s3));
        }
        mx0 = fmaxf(mx0, __shfl_xor_sync(0xffffffffu, mx0, 1));
        mx0 = fmaxf(mx0, __shfl_xor_sync(0xffffffffu, mx0, 2));
        mx1 = fmaxf(mx1, __shfl_xor_sync(0xffffffffu, mx1, 1));
        mx1 = fmaxf(mx1, __shfl_xor_sync(0xffffffffu, mx1, 2));

        float alpha0 = __expf(m_lo - mx0);
        float alpha1 = __expf(m_hi - mx1);
        float sum0 = 0.0f, sum1 = 0.0f;
#pragma unroll
        for (int bn = 0; bn < 8; bn++) {
            float p0 = __expf(sacc[bn][0] - mx0);
            float p1 = __expf(sacc[bn][1] - mx0);
            float p2 = __expf(sacc[bn][2] - mx1);
            float p3 = __expf(sacc[bn][3] - mx1);
            sacc[bn][0] = p0; sacc[bn][1] = p1; sacc[bn][2] = p2; sacc[bn][3] = p3;
            sum0 += p0 + p1; sum1 += p2 + p3;
        }
        sum0 += __shfl_xor_sync(0xffffffffu, sum0, 1);
        sum0 += __shfl_xor_sync(0xffffffffu, sum0, 2);
        sum1 += __shfl_xor_sync(0xffffffffu, sum1, 1);
        sum1 += __shfl_xor_sync(0xffffffffu, sum1, 2);
        l_lo = l_lo * alpha0 + sum0;
        l_hi = l_hi * alpha1 + sum1;
        m_lo = mx0; m_hi = mx1;
#pragma unroll
        for (int d = 0; d < 16; d++) {
            o[d][0] *= alpha0; o[d][1] *= alpha0;
            o[d][2] *= alpha1; o[d][3] *= alpha1;
        }

        // V(t) ready  (pending: K(t+1) if more)
        if (more) { CP_WAIT(1); } else { CP_WAIT(0); }
        __syncthreads();

        // ---- O += P V (3-term split)
#pragma unroll
        for (int ks2 = 0; ks2 < 4; ks2++) {
            uint32_t ah[4], al[4];
            split2(sacc[2*ks2][0],   sacc[2*ks2][1],   ah[0], al[0]);
            split2(sacc[2*ks2][2],   sacc[2*ks2][3],   ah[1], al[1]);
            split2(sacc[2*ks2+1][0], sacc[2*ks2+1][1], ah[2], al[2]);
            split2(sacc[2*ks2+1][2], sacc[2*ks2+1][3], ah[3], al[3]);
#pragma unroll
            for (int vp = 0; vp < 8; vp++) {
                uint32_t voff = (uint32_t)(ks2 * 16 + ((lane >> 3) & 1) * 8 + (lane & 7)) * FP
                              + (vp * 16 + (lane >> 4) * 8) * 2;
                uint32_t bh[4], bl[4];
                ldsm4t(bh[0], bh[1], bh[2], bh[3], Vh + voff);
                ldsm4t(bl[0], bl[1], bl[2], bl[3], Vl + voff);
                mma_bf16(o[2*vp],   ah, &bh[0]);
                mma_bf16(o[2*vp],   ah, &bl[0]);
                mma_bf16(o[2*vp],   al, &bh[0]);
                mma_bf16(o[2*vp+1], ah, &bh[2]);
                mma_bf16(o[2*vp+1], ah, &bl[2]);
                mma_bf16(o[2*vp+1], al, &bh[2]);
            }
        }
        __syncthreads();                 // all warps done reading V smem
        if (more) issueV(j0 + 64);       // prefetch next V over next QK
    }

    // ---- epilogue: normalize, write plain fp16
    float inv0 = 1.0f / l_lo, inv1 = 1.0f / l_hi;
    size_t base0 = (size_t)gi_lo * Q_SIZE + head * HEAD_DIM + (lane & 3) * 2;
    size_t base1 = base0 + (size_t)8 * Q_SIZE;
#pragma unroll
    for (int d = 0; d < 16; d++) {
        *(__half2*)(out_h + base0 + d * 8) = __floats2half2_rn(o[d][0] * inv0, o[d][1] * inv0);
        *(__half2*)(out_h + base1 + d * 8) = __floats2half2_rn(o[d][2] * inv1, o[d][3] * inv1);
    }
}

// ---------------------------------------------------------------------------
// Launch
// ---------------------------------------------------------------------------
extern "C" void kernel_launch(void* const* d_in, const int* in_sizes, int n_in,
                              void* d_out, int out_size)
{
    const float* hidden = (const float*)d_in[0];
    const float* w_qkv  = (const float*)d_in[1];
    const float* w_o    = (const float*)d_in[2];
    float* out = (float*)d_out;

    float *qkv, *cost, *sint;
    __half *hidh, *wqkvh, *woh, *attnh;
    __nv_bfloat16 *qh, *ql, *kh, *kl, *vh, *vl;
    cudaGetSymbolAddress((void**)&qkv, g_qkv);
    cudaGetSymbolAddress((void**)&cost, g_cos);
    cudaGetSymbolAddress((void**)&sint, g_sin);
    cudaGetSymbolAddress((void**)&hidh, g_hid_h);
    cudaGetSymbolAddress((void**)&wqkvh, g_wqkv_h);
    cudaGetSymbolAddress((void**)&woh, g_wo_h);
    cudaGetSymbolAddress((void**)&attnh, g_attn_h);
    cudaGetSymbolAddress((void**)&qh, g_q_hi);
    cudaGetSymbolAddress((void**)&ql, g_q_lo);
    cudaGetSymbolAddress((void**)&kh, g_k_hi);
    cudaGetSymbolAddress((void**)&kl, g_k_lo);
    cudaGetSymbolAddress((void**)&vh, g_v_hi);
    cudaGetSymbolAddress((void**)&vl, g_v_lo);

    cudaFuncSetAttribute(gemm_fp16, cudaFuncAttributeMaxDynamicSharedMemorySize, GEMM_SMEM);
    cudaFuncSetAttribute(flash_mma, cudaFuncAttributeMaxDynamicSharedMemorySize, FLASH_SMEM);

    // 0. RoPE table + fp16 input conversion
    rope_table<<<(S_LEN * 64 + 255) / 256, 256>>>(cost, sint);
    {
        int n1 = S_LEN * HIDDEN;
        cvt_fp16<<<n1 / 8 / 256, 256>>>(hidden, hidh, n1);
        int n2 = QKV_OUT * HIDDEN;
        cvt_fp16<<<n2 / 8 / 256, 256>>>(w_qkv, wqkvh, n2);
        int n3 = HIDDEN * HIDDEN;
        cvt_fp16<<<n3 / 8 / 256, 256>>>(w_o, woh, n3);
    }
    // 1. QKV projection (fp16 tensor cores)
    gemm_fp16<<<dim3(QKV_OUT / 128, S_LEN / 128), 256, GEMM_SMEM>>>(
        hidh, wqkvh, qkv, S_LEN, QKV_OUT, HIDDEN);
    // 2. RoPE + head-major split bf16
    {
        int total = S_LEN * 48 * 64;
        rope_split<<<(total + 255) / 256, 256>>>(qkv, cost, sint,
                                                 qh, ql, kh, kl, vh, vl);
    }
    // 3. Tensor-core flash attention -> fp16 output
    flash_mma<<<dim3(S_LEN / 64, NUM_HEADS), 128, FLASH_SMEM>>>(
        qh, ql, kh, kl, vh, vl, attnh);
    // 4. Output projection (fp16 tensor cores)
    gemm_fp16<<<dim3(HIDDEN / 128, S_LEN / 128), 256, GEMM_SMEM>>>(
        attnh, woh, out, S_LEN, HIDDEN, HIDDEN);
}